// round 2
// baseline (speedup 1.0000x reference)
#include <cuda_runtime.h>
#include <cuda_bf16.h>
#include <math.h>

// Problem constants
#define BATCH   2
#define SEQ     2048
#define DMODEL  2048
#define NHEADS  16
#define DK      128
#define ROWS    (BATCH * SEQ)          // 4096

// ---------------- scratch (static device globals: no runtime alloc) ----------
__device__ float g_Q[ROWS * DMODEL];
__device__ float g_K[ROWS * DMODEL];
__device__ float g_V[ROWS * DMODEL];
__device__ float g_AO[ROWS * DMODEL];

// ---------------- SGEMM: C[m,n] = sum_k A[m,k]*B[n,k] + bias[n] --------------
// A: [M,K] row-major, B: [N,K] row-major (i.e. C = A @ B^T), all fp32.
#define GBM 128
#define GBN 128
#define GBK 16

__global__ __launch_bounds__(256)
void sgemm_nt_bias(const float* __restrict__ A, const float* __restrict__ Bm,
                   const float* __restrict__ bias, float* __restrict__ C,
                   int M, int N, int K)
{
    __shared__ float As[GBK][GBM + 4];
    __shared__ float Bs[GBK][GBN + 4];

    const int tid = threadIdx.x;
    const int tx = tid & 15;
    const int ty = tid >> 4;
    const int m0 = blockIdx.y * GBM;
    const int n0 = blockIdx.x * GBN;

    float acc[8][8];
#pragma unroll
    for (int i = 0; i < 8; i++)
#pragma unroll
        for (int j = 0; j < 8; j++) acc[i][j] = 0.f;

    for (int k0 = 0; k0 < K; k0 += GBK) {
        // Load tiles: 128 rows x 16 cols = 512 float4 each, 2 per thread.
#pragma unroll
        for (int t = 0; t < 2; ++t) {
            int f = tid + t * 256;
            int row = f >> 2;            // 0..127
            int c4  = (f & 3) * 4;       // 0,4,8,12
            float4 av = *(const float4*)&A[(size_t)(m0 + row) * K + k0 + c4];
            As[c4 + 0][row] = av.x; As[c4 + 1][row] = av.y;
            As[c4 + 2][row] = av.z; As[c4 + 3][row] = av.w;
            float4 bv = *(const float4*)&Bm[(size_t)(n0 + row) * K + k0 + c4];
            Bs[c4 + 0][row] = bv.x; Bs[c4 + 1][row] = bv.y;
            Bs[c4 + 2][row] = bv.z; Bs[c4 + 3][row] = bv.w;
        }
        __syncthreads();

#pragma unroll
        for (int kk = 0; kk < GBK; ++kk) {
            float a[8], b[8];
            float4 a0 = *(float4*)&As[kk][ty * 8];
            float4 a1 = *(float4*)&As[kk][ty * 8 + 4];
            a[0]=a0.x; a[1]=a0.y; a[2]=a0.z; a[3]=a0.w;
            a[4]=a1.x; a[5]=a1.y; a[6]=a1.z; a[7]=a1.w;
            float4 b0 = *(float4*)&Bs[kk][tx * 8];
            float4 b1 = *(float4*)&Bs[kk][tx * 8 + 4];
            b[0]=b0.x; b[1]=b0.y; b[2]=b0.z; b[3]=b0.w;
            b[4]=b1.x; b[5]=b1.y; b[6]=b1.z; b[7]=b1.w;
#pragma unroll
            for (int i = 0; i < 8; i++)
#pragma unroll
                for (int j = 0; j < 8; j++)
                    acc[i][j] = fmaf(a[i], b[j], acc[i][j]);
        }
        __syncthreads();
    }

    // Epilogue with bias
#pragma unroll
    for (int i = 0; i < 8; i++) {
        int m = m0 + ty * 8 + i;
        float* crow = &C[(size_t)m * N + n0 + tx * 8];
        const float* brow = &bias[n0 + tx * 8];
        float4 r0, r1;
        r0.x = acc[i][0] + brow[0]; r0.y = acc[i][1] + brow[1];
        r0.z = acc[i][2] + brow[2]; r0.w = acc[i][3] + brow[3];
        r1.x = acc[i][4] + brow[4]; r1.y = acc[i][5] + brow[5];
        r1.z = acc[i][6] + brow[6]; r1.w = acc[i][7] + brow[7];
        *(float4*)&crow[0] = r0;
        *(float4*)&crow[4] = r1;
    }
}

// ---------------- RoPE (interleaved pairs, in place) -------------------------
__global__ __launch_bounds__(256)
void rope_kernel(float* __restrict__ buf)
{
    int idx = blockIdx.x * blockDim.x + threadIdx.x; // pair index
    const int total = ROWS * NHEADS * (DK / 2);
    if (idx >= total) return;
    int i   = idx & 63;            // freq index 0..63
    int h   = (idx >> 6) & 15;
    int row = idx >> 10;           // 0..4095
    int s   = row & (SEQ - 1);     // position

    float inv_freq = powf(10000.0f, -((float)(2 * i)) / 128.0f);
    float fr = (float)s * inv_freq;
    float c, sn;
    sincosf(fr, &sn, &c);

    float* p = buf + (size_t)row * DMODEL + h * DK + 2 * i;
    float e = p[0], o = p[1];
    p[0] = e * c - o * sn;
    p[1] = e * sn + o * c;
}

// ---------------- Flash attention (fp32, causal, online softmax) -------------
// Q,K,V,O layout: [b*S + s][h*128 + d]  (row stride DMODEL)
#define FA_BM 64
#define FA_BN 64
#define QS_STR 132
#define KS_STR 132
#define VS_STR 132
#define PS_STR 68

__global__ __launch_bounds__(256)
void flash_attn(const float* __restrict__ Q, const float* __restrict__ K,
                const float* __restrict__ V, float* __restrict__ O)
{
    extern __shared__ float sm[];
    float* Qs = sm;                       // 64*132
    float* Ks = Qs + 64 * QS_STR;         // 64*132
    float* Vs = Ks + 64 * KS_STR;         // 64*132
    float* Ps = Vs + 64 * VS_STR;         // 64*68
    float* scaleRow = Ps + 64 * PS_STR;   // 64
    float* lRow     = scaleRow + 64;      // 64

    const int tid  = threadIdx.x;
    const int tx   = tid & 15;
    const int ty   = tid >> 4;
    const int warp = tid >> 5;
    const int lane = tid & 31;

    const int qblk = blockIdx.x;          // 0..31
    const int bh   = blockIdx.y;          // 0..31
    const int b    = bh >> 4;
    const int h    = bh & 15;
    const int q0   = qblk * FA_BM;
    const size_t base = ((size_t)b * SEQ) * DMODEL + (size_t)h * DK;

    const float qscale = 0.08838834764831843f; // 1/sqrt(128)

    // Load Q tile (pre-scaled)
    for (int f = tid; f < 64 * 32; f += 256) {
        int r = f >> 5, c4 = (f & 31) * 4;
        float4 qv = *(const float4*)&Q[base + (size_t)(q0 + r) * DMODEL + c4];
        qv.x *= qscale; qv.y *= qscale; qv.z *= qscale; qv.w *= qscale;
        *(float4*)&Qs[r * QS_STR + c4] = qv;
    }

    float m_i[4], l_i[4];
#pragma unroll
    for (int i = 0; i < 4; i++) { m_i[i] = -INFINITY; l_i[i] = 0.f; }
    float o[8][4];
#pragma unroll
    for (int i = 0; i < 8; i++)
#pragma unroll
        for (int j = 0; j < 4; j++) o[i][j] = 0.f;

    __syncthreads();

    const int nblk = qblk + 1;
    for (int jb = 0; jb < nblk; ++jb) {
        const int k0 = jb * FA_BN;
        // Load K,V tiles
        for (int f = tid; f < 64 * 32; f += 256) {
            int r = f >> 5, c4 = (f & 31) * 4;
            *(float4*)&Ks[r * KS_STR + c4] =
                *(const float4*)&K[base + (size_t)(k0 + r) * DMODEL + c4];
            *(float4*)&Vs[r * VS_STR + c4] =
                *(const float4*)&V[base + (size_t)(k0 + r) * DMODEL + c4];
        }
        __syncthreads();

        // S tile: rows 4*ty+i, cols tx + 16*j
        float sacc[4][4];
#pragma unroll
        for (int i = 0; i < 4; i++)
#pragma unroll
            for (int j = 0; j < 4; j++) sacc[i][j] = 0.f;

#pragma unroll 8
        for (int kk = 0; kk < 128; kk += 4) {
            float4 qv[4], kv[4];
#pragma unroll
            for (int i = 0; i < 4; i++)
                qv[i] = *(float4*)&Qs[(4 * ty + i) * QS_STR + kk];
#pragma unroll
            for (int j = 0; j < 4; j++)
                kv[j] = *(float4*)&Ks[(tx + 16 * j) * KS_STR + kk];
#pragma unroll
            for (int i = 0; i < 4; i++)
#pragma unroll
                for (int j = 0; j < 4; j++) {
                    sacc[i][j] = fmaf(qv[i].x, kv[j].x, sacc[i][j]);
                    sacc[i][j] = fmaf(qv[i].y, kv[j].y, sacc[i][j]);
                    sacc[i][j] = fmaf(qv[i].z, kv[j].z, sacc[i][j]);
                    sacc[i][j] = fmaf(qv[i].w, kv[j].w, sacc[i][j]);
                }
        }

        // Causal mask (only the diagonal block needs it)
        if (jb == qblk) {
#pragma unroll
            for (int i = 0; i < 4; i++) {
                int qrow = q0 + 4 * ty + i;
#pragma unroll
                for (int j = 0; j < 4; j++) {
                    int kcol = k0 + tx + 16 * j;
                    if (kcol > qrow) sacc[i][j] = -INFINITY;
                }
            }
        }

        // Online softmax per row (replicated across 16 lanes of the row group)
#pragma unroll
        for (int i = 0; i < 4; i++) {
            float pm = fmaxf(fmaxf(sacc[i][0], sacc[i][1]),
                             fmaxf(sacc[i][2], sacc[i][3]));
#pragma unroll
            for (int off = 8; off >= 1; off >>= 1)
                pm = fmaxf(pm, __shfl_xor_sync(0xffffffffu, pm, off));
            float mnew = fmaxf(m_i[i], pm);
            float sc = __expf(m_i[i] - mnew);
            float psum = 0.f;
#pragma unroll
            for (int j = 0; j < 4; j++) {
                float p = __expf(sacc[i][j] - mnew);
                sacc[i][j] = p;
                psum += p;
            }
#pragma unroll
            for (int off = 8; off >= 1; off >>= 1)
                psum += __shfl_xor_sync(0xffffffffu, psum, off);
            l_i[i] = l_i[i] * sc + psum;
            m_i[i] = mnew;
            if (tx == 0) scaleRow[4 * ty + i] = sc;
#pragma unroll
            for (int j = 0; j < 4; j++)
                Ps[(4 * ty + i) * PS_STR + tx + 16 * j] = sacc[i][j];
        }
        __syncthreads();

        // O = O * scale + P @ V. Thread owns rows 8*warp..+7, cols 4*lane..+3.
#pragma unroll
        for (int i = 0; i < 8; i++) {
            float sc = scaleRow[8 * warp + i];
#pragma unroll
            for (int j = 0; j < 4; j++) o[i][j] *= sc;
        }
#pragma unroll 4
        for (int k = 0; k < 64; k += 4) {
            float4 vv[4];
#pragma unroll
            for (int kk = 0; kk < 4; kk++)
                vv[kk] = *(float4*)&Vs[(k + kk) * VS_STR + 4 * lane];
#pragma unroll
            for (int i = 0; i < 8; i++) {
                float4 pv = *(float4*)&Ps[(8 * warp + i) * PS_STR + k];
                o[i][0] = fmaf(pv.x, vv[0].x, o[i][0]);
                o[i][1] = fmaf(pv.x, vv[0].y, o[i][1]);
                o[i][2] = fmaf(pv.x, vv[0].z, o[i][2]);
                o[i][3] = fmaf(pv.x, vv[0].w, o[i][3]);
                o[i][0] = fmaf(pv.y, vv[1].x, o[i][0]);
                o[i][1] = fmaf(pv.y, vv[1].y, o[i][1]);
                o[i][2] = fmaf(pv.y, vv[1].z, o[i][2]);
                o[i][3] = fmaf(pv.y, vv[1].w, o[i][3]);
                o[i][0] = fmaf(pv.z, vv[2].x, o[i][0]);
                o[i][1] = fmaf(pv.z, vv[2].y, o[i][1]);
                o[i][2] = fmaf(pv.z, vv[2].z, o[i][2]);
                o[i][3] = fmaf(pv.z, vv[2].w, o[i][3]);
                o[i][0] = fmaf(pv.w, vv[3].x, o[i][0]);
                o[i][1] = fmaf(pv.w, vv[3].y, o[i][1]);
                o[i][2] = fmaf(pv.w, vv[3].z, o[i][2]);
                o[i][3] = fmaf(pv.w, vv[3].w, o[i][3]);
            }
        }
        __syncthreads();
    }

    // Publish l per row, then normalize + store
    if (tx == 0) {
#pragma unroll
        for (int i = 0; i < 4; i++) lRow[4 * ty + i] = l_i[i];
    }
    __syncthreads();

#pragma unroll
    for (int i = 0; i < 8; i++) {
        int r = 8 * warp + i;
        float inv = 1.0f / lRow[r];
        float4 ov;
        ov.x = o[i][0] * inv; ov.y = o[i][1] * inv;
        ov.z = o[i][2] * inv; ov.w = o[i][3] * inv;
        *(float4*)&O[base + (size_t)(q0 + r) * DMODEL + 4 * lane] = ov;
    }
}

// ---------------- launch ------------------------------------------------------
extern "C" void kernel_launch(void* const* d_in, const int* in_sizes, int n_in,
                              void* d_out, int out_size)
{
    const float* x    = (const float*)d_in[0];
    const float* wq_w = (const float*)d_in[1];
    const float* wq_b = (const float*)d_in[2];
    const float* wk_w = (const float*)d_in[3];
    const float* wk_b = (const float*)d_in[4];
    const float* wv_w = (const float*)d_in[5];
    const float* wv_b = (const float*)d_in[6];
    const float* wo_w = (const float*)d_in[7];
    const float* wo_b = (const float*)d_in[8];
    float* out = (float*)d_out;

    float *qb, *kb, *vb, *ab;
    cudaGetSymbolAddress((void**)&qb, g_Q);
    cudaGetSymbolAddress((void**)&kb, g_K);
    cudaGetSymbolAddress((void**)&vb, g_V);
    cudaGetSymbolAddress((void**)&ab, g_AO);

    dim3 ggrid(DMODEL / GBN, ROWS / GBM);   // (16, 32)
    sgemm_nt_bias<<<ggrid, 256>>>(x, wq_w, wq_b, qb, ROWS, DMODEL, DMODEL);
    sgemm_nt_bias<<<ggrid, 256>>>(x, wk_w, wk_b, kb, ROWS, DMODEL, DMODEL);
    sgemm_nt_bias<<<ggrid, 256>>>(x, wv_w, wv_b, vb, ROWS, DMODEL, DMODEL);

    int pairs = ROWS * NHEADS * (DK / 2);
    int rblocks = (pairs + 255) / 256;
    rope_kernel<<<rblocks, 256>>>(qb);
    rope_kernel<<<rblocks, 256>>>(kb);

    size_t fa_smem = (size_t)(3 * 64 * 132 + 64 * 68 + 128) * sizeof(float);
    cudaFuncSetAttribute(flash_attn, cudaFuncAttributeMaxDynamicSharedMemorySize,
                         (int)fa_smem);
    dim3 fgrid(SEQ / FA_BM, BATCH * NHEADS); // (32, 32)
    flash_attn<<<fgrid, 256, fa_smem>>>(qb, kb, vb, ab);

    sgemm_nt_bias<<<ggrid, 256>>>(ab, wo_w, wo_b, out, ROWS, DMODEL, DMODEL);
}

// round 3
// speedup vs baseline: 1.6660x; 1.6660x over previous
#include <cuda_runtime.h>
#include <cuda_bf16.h>
#include <math.h>
#include <stdint.h>

#define BATCH   2
#define SEQ     2048
#define DMODEL  2048
#define NHEADS  16
#define DK      128
#define ROWS    (BATCH * SEQ)          // 4096

// ---------------- scratch ----------------------------------------------------
__device__ float g_Q[ROWS * DMODEL];
__device__ float g_K[ROWS * DMODEL];
__device__ float g_V[ROWS * DMODEL];
__device__ float g_AO[ROWS * DMODEL];
__device__ __nv_bfloat16 g_xhi[ROWS * DMODEL],    g_xlo[ROWS * DMODEL];
__device__ __nv_bfloat16 g_whi[4][DMODEL * DMODEL], g_wlo[4][DMODEL * DMODEL];
__device__ __nv_bfloat16 g_ahi[ROWS * DMODEL],    g_alo[ROWS * DMODEL];

// ---------------- helpers ----------------------------------------------------
__device__ __forceinline__ uint32_t smem_u32(const void* p) {
    return (uint32_t)__cvta_generic_to_shared(p);
}
__device__ __forceinline__ void ldmx4(uint32_t& r0, uint32_t& r1, uint32_t& r2,
                                      uint32_t& r3, uint32_t a) {
    asm volatile("ldmatrix.sync.aligned.m8n8.x4.shared.b16 {%0,%1,%2,%3},[%4];"
                 : "=r"(r0), "=r"(r1), "=r"(r2), "=r"(r3) : "r"(a));
}
__device__ __forceinline__ void mma_bf(float* c, uint32_t a0, uint32_t a1,
                                       uint32_t a2, uint32_t a3,
                                       uint32_t b0, uint32_t b1) {
    asm volatile(
        "mma.sync.aligned.m16n8k16.row.col.f32.bf16.bf16.f32 "
        "{%0,%1,%2,%3},{%4,%5,%6,%7},{%8,%9},{%0,%1,%2,%3};"
        : "+f"(c[0]), "+f"(c[1]), "+f"(c[2]), "+f"(c[3])
        : "r"(a0), "r"(a1), "r"(a2), "r"(a3), "r"(b0), "r"(b1));
}
__device__ __forceinline__ void cpasync16(uint32_t dst, const void* src) {
    asm volatile("cp.async.cg.shared.global [%0],[%1],16;" :: "r"(dst), "l"(src));
}
#define CP_COMMIT asm volatile("cp.async.commit_group;")
template<int N> __device__ __forceinline__ void cp_wait() {
    asm volatile("cp.async.wait_group %0;" :: "n"(N));
}
__device__ __forceinline__ void split2(float v, __nv_bfloat16& h, __nv_bfloat16& l) {
    h = __float2bfloat16(v);
    l = __float2bfloat16(v - __bfloat162float(h));
}

// ---------------- convert fp32 -> hi/lo bf16 planes --------------------------
__global__ __launch_bounds__(256)
void convert_split(const float* __restrict__ in, __nv_bfloat16* __restrict__ hi,
                   __nv_bfloat16* __restrict__ lo)
{
    int i = (blockIdx.x * blockDim.x + threadIdx.x) * 4;
    float4 v = *(const float4*)(in + i);
    __nv_bfloat162 h0, h1, l0, l1;
    split2(v.x, h0.x, l0.x); split2(v.y, h0.y, l0.y);
    split2(v.z, h1.x, l1.x); split2(v.w, h1.y, l1.y);
    *(__nv_bfloat162*)&hi[i]     = h0;  *(__nv_bfloat162*)&hi[i + 2] = h1;
    *(__nv_bfloat162*)&lo[i]     = l0;  *(__nv_bfloat162*)&lo[i + 2] = l1;
}

// ---------------- bf16x3 GEMM: C = A @ B^T + bias (fp32 out) -----------------
// Planes: A [M][K], B [N][K]. Tiles 128x128x32, 8 warps.
#define NKIT (DMODEL / 32)      // 64
#define PLE  (128 * 40)         // elements per plane (rows padded to 40)
#define STGE (4 * PLE)          // elements per stage

__global__ __launch_bounds__(256, 1)
void gemm_bf16x3(const __nv_bfloat16* __restrict__ Ahi, const __nv_bfloat16* __restrict__ Alo,
                 const __nv_bfloat16* __restrict__ Bhi, const __nv_bfloat16* __restrict__ Blo,
                 const float* __restrict__ bias, float* __restrict__ C)
{
    extern __shared__ __nv_bfloat16 sm[];
    const int tid = threadIdx.x, lane = tid & 31, wid = tid >> 5;
    const int wm = wid & 3, wn = wid >> 2;        // 4x2 warp grid
    const int m0 = blockIdx.y * 128, n0 = blockIdx.x * 128;
    const uint32_t sb = smem_u32(sm);

    const __nv_bfloat16* srcs[4] = {Ahi, Alo, Bhi, Blo};

    auto issue = [&](int kt, int stg) {
        int kofs = kt * 32;
#pragma unroll
        for (int i = 0; i < 8; i++) {
            int idx = tid + i * 256;
            int plane = idx >> 9, rem = idx & 511;
            int row = rem >> 2, ch = (rem & 3) * 8;
            int grow = (plane < 2 ? m0 : n0) + row;
            const __nv_bfloat16* s = srcs[plane] + (size_t)grow * DMODEL + kofs + ch;
            cpasync16(sb + (stg * STGE + plane * PLE + row * 40 + ch) * 2, s);
        }
    };

    float acc[2][8][4];
#pragma unroll
    for (int a = 0; a < 2; a++)
#pragma unroll
        for (int b = 0; b < 8; b++)
#pragma unroll
            for (int c = 0; c < 4; c++) acc[a][b][c] = 0.f;

    issue(0, 0); CP_COMMIT;

    for (int kt = 0; kt < NKIT; kt++) {
        if (kt + 1 < NKIT) { issue(kt + 1, (kt + 1) & 1); CP_COMMIT; cp_wait<1>(); }
        else cp_wait<0>();
        __syncthreads();
        uint32_t s0 = sb + ((kt & 1) * STGE) * 2;

#pragma unroll
        for (int ks = 0; ks < 32; ks += 16) {
            // A frags (hi, lo) for 2 m16 tiles
            uint32_t ah[2][4], al[2][4];
#pragma unroll
            for (int mt = 0; mt < 2; mt++) {
                int ar = wm * 32 + mt * 16 + (lane & 15);
                int ac = ks + ((lane >> 4) << 3);
                uint32_t off = (uint32_t)(ar * 40 + ac) * 2;
                ldmx4(ah[mt][0], ah[mt][1], ah[mt][2], ah[mt][3], s0 + off);
                ldmx4(al[mt][0], al[mt][1], al[mt][2], al[mt][3], s0 + PLE * 2 + off);
            }
#pragma unroll
            for (int np = 0; np < 4; np++) {
                int br = wn * 64 + np * 16 + ((lane >> 4) << 3) + (lane & 7);
                int bc = ks + (((lane >> 3) & 1) << 3);
                uint32_t off = (uint32_t)(br * 40 + bc) * 2;
                uint32_t h0, h1, h2, h3, q0, q1, q2, q3;
                ldmx4(h0, h1, h2, h3, s0 + PLE * 4 + off);
                ldmx4(q0, q1, q2, q3, s0 + PLE * 6 + off);
#pragma unroll
                for (int mt = 0; mt < 2; mt++) {
                    float* c0 = acc[mt][2 * np];
                    float* c1 = acc[mt][2 * np + 1];
                    mma_bf(c0, ah[mt][0], ah[mt][1], ah[mt][2], ah[mt][3], h0, h1);
                    mma_bf(c0, ah[mt][0], ah[mt][1], ah[mt][2], ah[mt][3], q0, q1);
                    mma_bf(c0, al[mt][0], al[mt][1], al[mt][2], al[mt][3], h0, h1);
                    mma_bf(c1, ah[mt][0], ah[mt][1], ah[mt][2], ah[mt][3], h2, h3);
                    mma_bf(c1, ah[mt][0], ah[mt][1], ah[mt][2], ah[mt][3], q2, q3);
                    mma_bf(c1, al[mt][0], al[mt][1], al[mt][2], al[mt][3], h2, h3);
                }
            }
        }
        __syncthreads();
    }

    // epilogue: fp32 + bias
#pragma unroll
    for (int mt = 0; mt < 2; mt++) {
        int r = m0 + wm * 32 + mt * 16 + (lane >> 2);
#pragma unroll
        for (int nt = 0; nt < 8; nt++) {
            int gc = n0 + wn * 64 + nt * 8 + (lane & 3) * 2;
            float b0 = bias[gc], b1 = bias[gc + 1];
            float2 v0 = {acc[mt][nt][0] + b0, acc[mt][nt][1] + b1};
            float2 v1 = {acc[mt][nt][2] + b0, acc[mt][nt][3] + b1};
            *(float2*)&C[(size_t)r * DMODEL + gc] = v0;
            *(float2*)&C[(size_t)(r + 8) * DMODEL + gc] = v1;
        }
    }
}

// ---------------- RoPE (unchanged) -------------------------------------------
__global__ __launch_bounds__(256)
void rope_kernel(float* __restrict__ buf)
{
    int idx = blockIdx.x * blockDim.x + threadIdx.x;
    const int total = ROWS * NHEADS * (DK / 2);
    if (idx >= total) return;
    int i = idx & 63, h = (idx >> 6) & 15, row = idx >> 10, s = row & (SEQ - 1);
    float inv_freq = powf(10000.0f, -((float)(2 * i)) / 128.0f);
    float fr = (float)s * inv_freq, c, sn;
    sincosf(fr, &sn, &c);
    float* p = buf + (size_t)row * DMODEL + h * DK + 2 * i;
    float e = p[0], o = p[1];
    p[0] = e * c - o * sn;
    p[1] = e * sn + o * c;
}

// ---------------- Flash attention (fp32, unchanged from passing kernel) ------
#define FA_BM 64
#define FA_BN 64
#define QS_STR 132
#define PS_STR 68

__global__ __launch_bounds__(256)
void flash_attn(const float* __restrict__ Q, const float* __restrict__ K,
                const float* __restrict__ V, float* __restrict__ O)
{
    extern __shared__ float smf[];
    float* Qs = smf;
    float* Ks = Qs + 64 * QS_STR;
    float* Vs = Ks + 64 * QS_STR;
    float* Ps = Vs + 64 * QS_STR;
    float* scaleRow = Ps + 64 * PS_STR;
    float* lRow     = scaleRow + 64;

    const int tid = threadIdx.x, tx = tid & 15, ty = tid >> 4;
    const int warp = tid >> 5, lane = tid & 31;
    const int qblk = blockIdx.x, bh = blockIdx.y;
    const int b = bh >> 4, h = bh & 15, q0 = qblk * FA_BM;
    const size_t base = ((size_t)b * SEQ) * DMODEL + (size_t)h * DK;
    const float qscale = 0.08838834764831843f;

    for (int f = tid; f < 64 * 32; f += 256) {
        int r = f >> 5, c4 = (f & 31) * 4;
        float4 qv = *(const float4*)&Q[base + (size_t)(q0 + r) * DMODEL + c4];
        qv.x *= qscale; qv.y *= qscale; qv.z *= qscale; qv.w *= qscale;
        *(float4*)&Qs[r * QS_STR + c4] = qv;
    }

    float m_i[4], l_i[4];
#pragma unroll
    for (int i = 0; i < 4; i++) { m_i[i] = -INFINITY; l_i[i] = 0.f; }
    float o[8][4];
#pragma unroll
    for (int i = 0; i < 8; i++)
#pragma unroll
        for (int j = 0; j < 4; j++) o[i][j] = 0.f;
    __syncthreads();

    for (int jb = 0; jb <= qblk; ++jb) {
        const int k0 = jb * FA_BN;
        for (int f = tid; f < 64 * 32; f += 256) {
            int r = f >> 5, c4 = (f & 31) * 4;
            *(float4*)&Ks[r * QS_STR + c4] =
                *(const float4*)&K[base + (size_t)(k0 + r) * DMODEL + c4];
            *(float4*)&Vs[r * QS_STR + c4] =
                *(const float4*)&V[base + (size_t)(k0 + r) * DMODEL + c4];
        }
        __syncthreads();

        float sacc[4][4];
#pragma unroll
        for (int i = 0; i < 4; i++)
#pragma unroll
            for (int j = 0; j < 4; j++) sacc[i][j] = 0.f;

#pragma unroll 8
        for (int kk = 0; kk < 128; kk += 4) {
            float4 qv[4], kv[4];
#pragma unroll
            for (int i = 0; i < 4; i++)
                qv[i] = *(float4*)&Qs[(4 * ty + i) * QS_STR + kk];
#pragma unroll
            for (int j = 0; j < 4; j++)
                kv[j] = *(float4*)&Ks[(tx + 16 * j) * QS_STR + kk];
#pragma unroll
            for (int i = 0; i < 4; i++)
#pragma unroll
                for (int j = 0; j < 4; j++) {
                    sacc[i][j] = fmaf(qv[i].x, kv[j].x, sacc[i][j]);
                    sacc[i][j] = fmaf(qv[i].y, kv[j].y, sacc[i][j]);
                    sacc[i][j] = fmaf(qv[i].z, kv[j].z, sacc[i][j]);
                    sacc[i][j] = fmaf(qv[i].w, kv[j].w, sacc[i][j]);
                }
        }

        if (jb == qblk) {
#pragma unroll
            for (int i = 0; i < 4; i++) {
                int qrow = q0 + 4 * ty + i;
#pragma unroll
                for (int j = 0; j < 4; j++)
                    if (k0 + tx + 16 * j > qrow) sacc[i][j] = -INFINITY;
            }
        }

#pragma unroll
        for (int i = 0; i < 4; i++) {
            float pm = fmaxf(fmaxf(sacc[i][0], sacc[i][1]),
                             fmaxf(sacc[i][2], sacc[i][3]));
#pragma unroll
            for (int off = 8; off >= 1; off >>= 1)
                pm = fmaxf(pm, __shfl_xor_sync(0xffffffffu, pm, off));
            float mnew = fmaxf(m_i[i], pm);
            float sc = __expf(m_i[i] - mnew);
            float psum = 0.f;
#pragma unroll
            for (int j = 0; j < 4; j++) {
                float p = __expf(sacc[i][j] - mnew);
                sacc[i][j] = p;
                psum += p;
            }
#pragma unroll
            for (int off = 8; off >= 1; off >>= 1)
                psum += __shfl_xor_sync(0xffffffffu, psum, off);
            l_i[i] = l_i[i] * sc + psum;
            m_i[i] = mnew;
            if (tx == 0) scaleRow[4 * ty + i] = sc;
#pragma unroll
            for (int j = 0; j < 4; j++)
                Ps[(4 * ty + i) * PS_STR + tx + 16 * j] = sacc[i][j];
        }
        __syncthreads();

#pragma unroll
        for (int i = 0; i < 8; i++) {
            float sc = scaleRow[8 * warp + i];
#pragma unroll
            for (int j = 0; j < 4; j++) o[i][j] *= sc;
        }
#pragma unroll 4
        for (int k = 0; k < 64; k += 4) {
            float4 vv[4];
#pragma unroll
            for (int kk = 0; kk < 4; kk++)
                vv[kk] = *(float4*)&Vs[(k + kk) * QS_STR + 4 * lane];
#pragma unroll
            for (int i = 0; i < 8; i++) {
                float4 pv = *(float4*)&Ps[(8 * warp + i) * PS_STR + k];
                float pr[4] = {pv.x, pv.y, pv.z, pv.w};
#pragma unroll
                for (int kk = 0; kk < 4; kk++) {
                    o[i][0] = fmaf(pr[kk], vv[kk].x, o[i][0]);
                    o[i][1] = fmaf(pr[kk], vv[kk].y, o[i][1]);
                    o[i][2] = fmaf(pr[kk], vv[kk].z, o[i][2]);
                    o[i][3] = fmaf(pr[kk], vv[kk].w, o[i][3]);
                }
            }
        }
        __syncthreads();
    }

    if (tx == 0)
#pragma unroll
        for (int i = 0; i < 4; i++) lRow[4 * ty + i] = l_i[i];
    __syncthreads();

#pragma unroll
    for (int i = 0; i < 8; i++) {
        int r = 8 * warp + i;
        float inv = 1.0f / lRow[r];
        float4 ov = {o[i][0] * inv, o[i][1] * inv, o[i][2] * inv, o[i][3] * inv};
        *(float4*)&O[base + (size_t)(q0 + r) * DMODEL + 4 * lane] = ov;
    }
}

// ---------------- launch ------------------------------------------------------
extern "C" void kernel_launch(void* const* d_in, const int* in_sizes, int n_in,
                              void* d_out, int out_size)
{
    const float* x    = (const float*)d_in[0];
    const float* w[4] = {(const float*)d_in[1], (const float*)d_in[3],
                         (const float*)d_in[5], (const float*)d_in[7]};
    const float* bi[4] = {(const float*)d_in[2], (const float*)d_in[4],
                          (const float*)d_in[6], (const float*)d_in[8]};
    float* out = (float*)d_out;

    float *qb, *kb, *vb, *ab;
    cudaGetSymbolAddress((void**)&qb, g_Q);
    cudaGetSymbolAddress((void**)&kb, g_K);
    cudaGetSymbolAddress((void**)&vb, g_V);
    cudaGetSymbolAddress((void**)&ab, g_AO);
    __nv_bfloat16 *xh, *xl, *wh, *wl, *ah, *al;
    cudaGetSymbolAddress((void**)&xh, g_xhi);
    cudaGetSymbolAddress((void**)&xl, g_xlo);
    cudaGetSymbolAddress((void**)&wh, g_whi);
    cudaGetSymbolAddress((void**)&wl, g_wlo);
    cudaGetSymbolAddress((void**)&ah, g_ahi);
    cudaGetSymbolAddress((void**)&al, g_alo);

    const size_t WN = (size_t)DMODEL * DMODEL;
    convert_split<<<ROWS * DMODEL / 1024, 256>>>(x, xh, xl);
    for (int i = 0; i < 4; i++)
        convert_split<<<WN / 1024, 256>>>(w[i], wh + i * WN, wl + i * WN);

    size_t gsmem = 2 * STGE * sizeof(__nv_bfloat16);   // 81920
    cudaFuncSetAttribute(gemm_bf16x3, cudaFuncAttributeMaxDynamicSharedMemorySize,
                         (int)gsmem);
    dim3 ggrid(DMODEL / 128, ROWS / 128);              // (16, 32)
    gemm_bf16x3<<<ggrid, 256, gsmem>>>(xh, xl, wh + 0 * WN, wl + 0 * WN, bi[0], qb);
    gemm_bf16x3<<<ggrid, 256, gsmem>>>(xh, xl, wh + 1 * WN, wl + 1 * WN, bi[1], kb);
    gemm_bf16x3<<<ggrid, 256, gsmem>>>(xh, xl, wh + 2 * WN, wl + 2 * WN, bi[2], vb);

    int pairs = ROWS * NHEADS * (DK / 2);
    rope_kernel<<<(pairs + 255) / 256, 256>>>(qb);
    rope_kernel<<<(pairs + 255) / 256, 256>>>(kb);

    size_t fa_smem = (size_t)(3 * 64 * QS_STR + 64 * PS_STR + 128) * sizeof(float);
    cudaFuncSetAttribute(flash_attn, cudaFuncAttributeMaxDynamicSharedMemorySize,
                         (int)fa_smem);
    dim3 fgrid(SEQ / FA_BM, BATCH * NHEADS);
    flash_attn<<<fgrid, 256, fa_smem>>>(qb, kb, vb, ab);

    convert_split<<<ROWS * DMODEL / 1024, 256>>>(ab, ah, al);
    gemm_bf16x3<<<ggrid, 256, gsmem>>>(ah, al, wh + 3 * WN, wl + 3 * WN, bi[3], out);
}

// round 4
// speedup vs baseline: 2.3059x; 1.3841x over previous
#include <cuda_runtime.h>
#include <cuda_bf16.h>
#include <math.h>
#include <stdint.h>

#define BATCH   2
#define SEQ     2048
#define DMODEL  2048
#define NHEADS  16
#define DK      128
#define ROWS    (BATCH * SEQ)

// ---------------- scratch ----------------------------------------------------
__device__ float g_Q[ROWS * DMODEL];
__device__ float g_K[ROWS * DMODEL];
__device__ float g_V[ROWS * DMODEL];
__device__ float g_AO[ROWS * DMODEL];
__device__ __nv_bfloat16 g_xhi[ROWS * DMODEL],    g_xlo[ROWS * DMODEL];
__device__ __nv_bfloat16 g_whi[4][DMODEL * DMODEL], g_wlo[4][DMODEL * DMODEL];
__device__ __nv_bfloat16 g_ahi[ROWS * DMODEL],    g_alo[ROWS * DMODEL];
__device__ __nv_bfloat16 g_qhi[ROWS * DMODEL],    g_qlo[ROWS * DMODEL];
__device__ __nv_bfloat16 g_khi[ROWS * DMODEL],    g_klo[ROWS * DMODEL];
__device__ __nv_bfloat16 g_vthi[ROWS * DMODEL],   g_vtlo[ROWS * DMODEL]; // [bh][d][s]

// ---------------- helpers ----------------------------------------------------
__device__ __forceinline__ uint32_t smem_u32(const void* p) {
    return (uint32_t)__cvta_generic_to_shared(p);
}
__device__ __forceinline__ void ldmx4(uint32_t& r0, uint32_t& r1, uint32_t& r2,
                                      uint32_t& r3, uint32_t a) {
    asm volatile("ldmatrix.sync.aligned.m8n8.x4.shared.b16 {%0,%1,%2,%3},[%4];"
                 : "=r"(r0), "=r"(r1), "=r"(r2), "=r"(r3) : "r"(a));
}
__device__ __forceinline__ void mma_bf(float* c, uint32_t a0, uint32_t a1,
                                       uint32_t a2, uint32_t a3,
                                       uint32_t b0, uint32_t b1) {
    asm volatile(
        "mma.sync.aligned.m16n8k16.row.col.f32.bf16.bf16.f32 "
        "{%0,%1,%2,%3},{%4,%5,%6,%7},{%8,%9},{%0,%1,%2,%3};"
        : "+f"(c[0]), "+f"(c[1]), "+f"(c[2]), "+f"(c[3])
        : "r"(a0), "r"(a1), "r"(a2), "r"(a3), "r"(b0), "r"(b1));
}
__device__ __forceinline__ void cpasync16(uint32_t dst, const void* src) {
    asm volatile("cp.async.cg.shared.global [%0],[%1],16;" :: "r"(dst), "l"(src));
}
#define CP_COMMIT asm volatile("cp.async.commit_group;")
template<int N> __device__ __forceinline__ void cp_wait() {
    asm volatile("cp.async.wait_group %0;" :: "n"(N));
}
__device__ __forceinline__ void split2(float v, __nv_bfloat16& h, __nv_bfloat16& l) {
    h = __float2bfloat16(v);
    l = __float2bfloat16(v - __bfloat162float(h));
}
__device__ __forceinline__ void splitpack(float x, float y, uint32_t& h, uint32_t& l) {
    __nv_bfloat162 hh, ll;
    split2(x, hh.x, ll.x); split2(y, hh.y, ll.y);
    h = *(uint32_t*)&hh; l = *(uint32_t*)&ll;
}

// ---------------- convert fp32 -> hi/lo bf16 planes --------------------------
__global__ __launch_bounds__(256)
void convert_split(const float* __restrict__ in, __nv_bfloat16* __restrict__ hi,
                   __nv_bfloat16* __restrict__ lo)
{
    int i = (blockIdx.x * blockDim.x + threadIdx.x) * 4;
    float4 v = *(const float4*)(in + i);
    __nv_bfloat162 h0, h1, l0, l1;
    split2(v.x, h0.x, l0.x); split2(v.y, h0.y, l0.y);
    split2(v.z, h1.x, l1.x); split2(v.w, h1.y, l1.y);
    *(__nv_bfloat162*)&hi[i]     = h0;  *(__nv_bfloat162*)&hi[i + 2] = h1;
    *(__nv_bfloat162*)&lo[i]     = l0;  *(__nv_bfloat162*)&lo[i + 2] = l1;
}

// ---------------- V -> transposed per-head planes [bh][d][s] -----------------
__global__ __launch_bounds__(256)
void convert_vt(const float* __restrict__ V, __nv_bfloat16* __restrict__ hi,
                __nv_bfloat16* __restrict__ lo)
{
    __shared__ float t[32][33];
    int bh = blockIdx.z, b = bh >> 4, h = bh & 15;
    int s0 = blockIdx.x * 32, d0 = blockIdx.y * 32;
    int lx = threadIdx.x & 31, ly = threadIdx.x >> 5;
#pragma unroll
    for (int i = 0; i < 4; i++) {
        int sl = ly + i * 8;
        t[sl][lx] = V[(size_t)(b * SEQ + s0 + sl) * DMODEL + h * DK + d0 + lx];
    }
    __syncthreads();
#pragma unroll
    for (int i = 0; i < 4; i++) {
        int dl = ly + i * 8;
        float v = t[lx][dl];
        __nv_bfloat16 hh, ll; split2(v, hh, ll);
        size_t o = (size_t)(bh * DK + d0 + dl) * SEQ + s0 + lx;
        hi[o] = hh; lo[o] = ll;
    }
}

// ---------------- bf16x3 GEMM (unchanged) ------------------------------------
#define NKIT (DMODEL / 32)
#define PLE  (128 * 40)
#define STGE (4 * PLE)

__global__ __launch_bounds__(256, 1)
void gemm_bf16x3(const __nv_bfloat16* __restrict__ Ahi, const __nv_bfloat16* __restrict__ Alo,
                 const __nv_bfloat16* __restrict__ Bhi, const __nv_bfloat16* __restrict__ Blo,
                 const float* __restrict__ bias, float* __restrict__ C)
{
    extern __shared__ __nv_bfloat16 sm[];
    const int tid = threadIdx.x, lane = tid & 31, wid = tid >> 5;
    const int wm = wid & 3, wn = wid >> 2;
    const int m0 = blockIdx.y * 128, n0 = blockIdx.x * 128;
    const uint32_t sb = smem_u32(sm);
    const __nv_bfloat16* srcs[4] = {Ahi, Alo, Bhi, Blo};

    auto issue = [&](int kt, int stg) {
        int kofs = kt * 32;
#pragma unroll
        for (int i = 0; i < 8; i++) {
            int idx = tid + i * 256;
            int plane = idx >> 9, rem = idx & 511;
            int row = rem >> 2, ch = (rem & 3) * 8;
            int grow = (plane < 2 ? m0 : n0) + row;
            cpasync16(sb + (stg * STGE + plane * PLE + row * 40 + ch) * 2,
                      srcs[plane] + (size_t)grow * DMODEL + kofs + ch);
        }
    };

    float acc[2][8][4];
#pragma unroll
    for (int a = 0; a < 2; a++)
#pragma unroll
        for (int b = 0; b < 8; b++)
#pragma unroll
            for (int c = 0; c < 4; c++) acc[a][b][c] = 0.f;

    issue(0, 0); CP_COMMIT;
    for (int kt = 0; kt < NKIT; kt++) {
        if (kt + 1 < NKIT) { issue(kt + 1, (kt + 1) & 1); CP_COMMIT; cp_wait<1>(); }
        else cp_wait<0>();
        __syncthreads();
        uint32_t s0 = sb + ((kt & 1) * STGE) * 2;
#pragma unroll
        for (int ks = 0; ks < 32; ks += 16) {
            uint32_t ah[2][4], al[2][4];
#pragma unroll
            for (int mt = 0; mt < 2; mt++) {
                int ar = wm * 32 + mt * 16 + (lane & 15);
                int ac = ks + ((lane >> 4) << 3);
                uint32_t off = (uint32_t)(ar * 40 + ac) * 2;
                ldmx4(ah[mt][0], ah[mt][1], ah[mt][2], ah[mt][3], s0 + off);
                ldmx4(al[mt][0], al[mt][1], al[mt][2], al[mt][3], s0 + PLE * 2 + off);
            }
#pragma unroll
            for (int np = 0; np < 4; np++) {
                int br = wn * 64 + np * 16 + ((lane >> 4) << 3) + (lane & 7);
                int bc = ks + (((lane >> 3) & 1) << 3);
                uint32_t off = (uint32_t)(br * 40 + bc) * 2;
                uint32_t h0, h1, h2, h3, q0, q1, q2, q3;
                ldmx4(h0, h1, h2, h3, s0 + PLE * 4 + off);
                ldmx4(q0, q1, q2, q3, s0 + PLE * 6 + off);
#pragma unroll
                for (int mt = 0; mt < 2; mt++) {
                    float* c0 = acc[mt][2 * np];
                    float* c1 = acc[mt][2 * np + 1];
                    mma_bf(c0, ah[mt][0], ah[mt][1], ah[mt][2], ah[mt][3], h0, h1);
                    mma_bf(c0, ah[mt][0], ah[mt][1], ah[mt][2], ah[mt][3], q0, q1);
                    mma_bf(c0, al[mt][0], al[mt][1], al[mt][2], al[mt][3], h0, h1);
                    mma_bf(c1, ah[mt][0], ah[mt][1], ah[mt][2], ah[mt][3], h2, h3);
                    mma_bf(c1, ah[mt][0], ah[mt][1], ah[mt][2], ah[mt][3], q2, q3);
                    mma_bf(c1, al[mt][0], al[mt][1], al[mt][2], al[mt][3], h2, h3);
                }
            }
        }
        __syncthreads();
    }
#pragma unroll
    for (int mt = 0; mt < 2; mt++) {
        int r = m0 + wm * 32 + mt * 16 + (lane >> 2);
#pragma unroll
        for (int nt = 0; nt < 8; nt++) {
            int gc = n0 + wn * 64 + nt * 8 + (lane & 3) * 2;
            float b0 = bias[gc], b1 = bias[gc + 1];
            float2 v0 = {acc[mt][nt][0] + b0, acc[mt][nt][1] + b1};
            float2 v1 = {acc[mt][nt][2] + b0, acc[mt][nt][3] + b1};
            *(float2*)&C[(size_t)r * DMODEL + gc] = v0;
            *(float2*)&C[(size_t)(r + 8) * DMODEL + gc] = v1;
        }
    }
}

// ---------------- RoPE (fp32, with output scale) -----------------------------
__global__ __launch_bounds__(256)
void rope_kernel(float* __restrict__ buf, float outscale)
{
    int idx = blockIdx.x * blockDim.x + threadIdx.x;
    const int total = ROWS * NHEADS * (DK / 2);
    if (idx >= total) return;
    int i = idx & 63, h = (idx >> 6) & 15, row = idx >> 10, s = row & (SEQ - 1);
    float inv_freq = powf(10000.0f, -((float)(2 * i)) / 128.0f);
    float fr = (float)s * inv_freq, c, sn;
    sincosf(fr, &sn, &c);
    float* p = buf + (size_t)row * DMODEL + h * DK + 2 * i;
    float e = p[0], o = p[1];
    p[0] = (e * c - o * sn) * outscale;
    p[1] = (e * sn + o * c) * outscale;
}

// ---------------- Flash attention on tensor cores ----------------------------
// BM=64 q rows (4 warps x m16), BN=64 keys. smem offsets in bf16 elems:
#define FQH 0
#define FQL 8704
#define FKH 17408
#define FKL 26112
#define FVH 34816
#define FVL 44032
#define FTOT 53248

__global__ __launch_bounds__(128, 2)
void flash_mma(const __nv_bfloat16* __restrict__ Qh, const __nv_bfloat16* __restrict__ Ql,
               const __nv_bfloat16* __restrict__ Kh, const __nv_bfloat16* __restrict__ Kl,
               const __nv_bfloat16* __restrict__ Vh, const __nv_bfloat16* __restrict__ Vl,
               float* __restrict__ O)
{
    extern __shared__ __nv_bfloat16 sm[];
    const uint32_t sb = smem_u32(sm);
    const int tid = threadIdx.x, lane = tid & 31, warp = tid >> 5;
    const int qblk = blockIdx.x, bh = blockIdx.y;
    const int b = bh >> 4, h = bh & 15, q0 = qblk * 64;
    const int hofs = h * DK;
    const size_t qrow0 = (size_t)(b * SEQ + q0);
    const __nv_bfloat16* vtbase_h = Vh + (size_t)bh * DK * SEQ;
    const __nv_bfloat16* vtbase_l = Vl + (size_t)bh * DK * SEQ;

    // load Q tile (hi/lo) once
#pragma unroll
    for (int i = 0; i < 8; i++) {
        int idx = tid + i * 128;
        int r = idx >> 4, c = (idx & 15) * 8;
        cpasync16(sb + (FQH + r * 136 + c) * 2, Qh + (qrow0 + r) * DMODEL + hofs + c);
        cpasync16(sb + (FQL + r * 136 + c) * 2, Ql + (qrow0 + r) * DMODEL + hofs + c);
    }
    CP_COMMIT;

    float o[16][4];
#pragma unroll
    for (int t = 0; t < 16; t++)
#pragma unroll
        for (int e = 0; e < 4; e++) o[t][e] = 0.f;
    float m0v = -INFINITY, m1v = -INFINITY, l0v = 0.f, l1v = 0.f;

    for (int jb = 0; jb <= qblk; ++jb) {
        const int k0 = jb * 64;
        const size_t krow0 = (size_t)(b * SEQ + k0);
#pragma unroll
        for (int i = 0; i < 8; i++) {
            int idx = tid + i * 128;
            int r = idx >> 4, c = (idx & 15) * 8;
            cpasync16(sb + (FKH + r * 136 + c) * 2, Kh + (krow0 + r) * DMODEL + hofs + c);
            cpasync16(sb + (FKL + r * 136 + c) * 2, Kl + (krow0 + r) * DMODEL + hofs + c);
        }
#pragma unroll
        for (int i = 0; i < 8; i++) {
            int idx = tid + i * 128;
            int d = idx >> 3, c = (idx & 7) * 8;
            cpasync16(sb + (FVH + d * 72 + c) * 2, vtbase_h + (size_t)d * SEQ + k0 + c);
            cpasync16(sb + (FVL + d * 72 + c) * 2, vtbase_l + (size_t)d * SEQ + k0 + c);
        }
        CP_COMMIT; cp_wait<0>();
        __syncthreads();

        float s[8][4];
#pragma unroll
        for (int t = 0; t < 8; t++)
#pragma unroll
            for (int e = 0; e < 4; e++) s[t][e] = 0.f;

#pragma unroll
        for (int kc = 0; kc < 8; kc++) {
            int ar = warp * 16 + (lane & 15);
            int ac = kc * 16 + ((lane >> 4) << 3);
            uint32_t aoff = (uint32_t)(ar * 136 + ac) * 2;
            uint32_t qh0, qh1, qh2, qh3, ql0, ql1, ql2, ql3;
            ldmx4(qh0, qh1, qh2, qh3, sb + FQH * 2 + aoff);
            ldmx4(ql0, ql1, ql2, ql3, sb + FQL * 2 + aoff);
#pragma unroll
            for (int np = 0; np < 4; np++) {
                int br = np * 16 + ((lane >> 4) << 3) + (lane & 7);
                int bc = kc * 16 + (((lane >> 3) & 1) << 3);
                uint32_t boff = (uint32_t)(br * 136 + bc) * 2;
                uint32_t kh0, kh1, kh2, kh3, kl0, kl1, kl2, kl3;
                ldmx4(kh0, kh1, kh2, kh3, sb + FKH * 2 + boff);
                ldmx4(kl0, kl1, kl2, kl3, sb + FKL * 2 + boff);
                mma_bf(s[2 * np],     qh0, qh1, qh2, qh3, kh0, kh1);
                mma_bf(s[2 * np],     ql0, ql1, ql2, ql3, kh0, kh1);
                mma_bf(s[2 * np],     qh0, qh1, qh2, qh3, kl0, kl1);
                mma_bf(s[2 * np + 1], qh0, qh1, qh2, qh3, kh2, kh3);
                mma_bf(s[2 * np + 1], ql0, ql1, ql2, ql3, kh2, kh3);
                mma_bf(s[2 * np + 1], qh0, qh1, qh2, qh3, kl2, kl3);
            }
        }

        if (jb == qblk) {
            int r0 = q0 + warp * 16 + (lane >> 2);
#pragma unroll
            for (int t = 0; t < 8; t++) {
                int c0 = k0 + t * 8 + 2 * (lane & 3);
                if (c0 > r0)     s[t][0] = -INFINITY;
                if (c0 + 1 > r0) s[t][1] = -INFINITY;
                if (c0 > r0 + 8)     s[t][2] = -INFINITY;
                if (c0 + 1 > r0 + 8) s[t][3] = -INFINITY;
            }
        }

        float mx0 = -INFINITY, mx1 = -INFINITY;
#pragma unroll
        for (int t = 0; t < 8; t++) {
            mx0 = fmaxf(mx0, fmaxf(s[t][0], s[t][1]));
            mx1 = fmaxf(mx1, fmaxf(s[t][2], s[t][3]));
        }
        mx0 = fmaxf(mx0, __shfl_xor_sync(0xffffffffu, mx0, 1));
        mx0 = fmaxf(mx0, __shfl_xor_sync(0xffffffffu, mx0, 2));
        mx1 = fmaxf(mx1, __shfl_xor_sync(0xffffffffu, mx1, 1));
        mx1 = fmaxf(mx1, __shfl_xor_sync(0xffffffffu, mx1, 2));
        float mn0 = fmaxf(m0v, mx0), mn1 = fmaxf(m1v, mx1);
        float sc0 = __expf(m0v - mn0), sc1 = __expf(m1v - mn1);
        float sum0 = 0.f, sum1 = 0.f;
#pragma unroll
        for (int t = 0; t < 8; t++) {
            s[t][0] = __expf(s[t][0] - mn0); sum0 += s[t][0];
            s[t][1] = __expf(s[t][1] - mn0); sum0 += s[t][1];
            s[t][2] = __expf(s[t][2] - mn1); sum1 += s[t][2];
            s[t][3] = __expf(s[t][3] - mn1); sum1 += s[t][3];
        }
        sum0 += __shfl_xor_sync(0xffffffffu, sum0, 1);
        sum0 += __shfl_xor_sync(0xffffffffu, sum0, 2);
        sum1 += __shfl_xor_sync(0xffffffffu, sum1, 1);
        sum1 += __shfl_xor_sync(0xffffffffu, sum1, 2);
        l0v = l0v * sc0 + sum0; m0v = mn0;
        l1v = l1v * sc1 + sum1; m1v = mn1;

#pragma unroll
        for (int t = 0; t < 16; t++) {
            o[t][0] *= sc0; o[t][1] *= sc0; o[t][2] *= sc1; o[t][3] *= sc1;
        }

        // P @ V
#pragma unroll
        for (int kc = 0; kc < 4; kc++) {
            uint32_t ah0, ah1, ah2, ah3, al0, al1, al2, al3;
            splitpack(s[2 * kc][0],     s[2 * kc][1],     ah0, al0);
            splitpack(s[2 * kc][2],     s[2 * kc][3],     ah1, al1);
            splitpack(s[2 * kc + 1][0], s[2 * kc + 1][1], ah2, al2);
            splitpack(s[2 * kc + 1][2], s[2 * kc + 1][3], ah3, al3);
#pragma unroll
            for (int np = 0; np < 8; np++) {
                int br = np * 16 + ((lane >> 4) << 3) + (lane & 7);
                int bc = kc * 16 + (((lane >> 3) & 1) << 3);
                uint32_t boff = (uint32_t)(br * 72 + bc) * 2;
                uint32_t vh0, vh1, vh2, vh3, vl0, vl1, vl2, vl3;
                ldmx4(vh0, vh1, vh2, vh3, sb + FVH * 2 + boff);
                ldmx4(vl0, vl1, vl2, vl3, sb + FVL * 2 + boff);
                mma_bf(o[2 * np],     ah0, ah1, ah2, ah3, vh0, vh1);
                mma_bf(o[2 * np],     al0, al1, al2, al3, vh0, vh1);
                mma_bf(o[2 * np],     ah0, ah1, ah2, ah3, vl0, vl1);
                mma_bf(o[2 * np + 1], ah0, ah1, ah2, ah3, vh2, vh3);
                mma_bf(o[2 * np + 1], al0, al1, al2, al3, vh2, vh3);
                mma_bf(o[2 * np + 1], ah0, ah1, ah2, ah3, vl2, vl3);
            }
        }
        __syncthreads();
    }

    float inv0 = 1.f / l0v, inv1 = 1.f / l1v;
    int r0 = b * SEQ + q0 + warp * 16 + (lane >> 2);
#pragma unroll
    for (int t = 0; t < 16; t++) {
        int gc = hofs + t * 8 + 2 * (lane & 3);
        float2 v0 = {o[t][0] * inv0, o[t][1] * inv0};
        float2 v1 = {o[t][2] * inv1, o[t][3] * inv1};
        *(float2*)&O[(size_t)r0 * DMODEL + gc] = v0;
        *(float2*)&O[(size_t)(r0 + 8) * DMODEL + gc] = v1;
    }
}

// ---------------- launch ------------------------------------------------------
extern "C" void kernel_launch(void* const* d_in, const int* in_sizes, int n_in,
                              void* d_out, int out_size)
{
    const float* x    = (const float*)d_in[0];
    const float* w[4] = {(const float*)d_in[1], (const float*)d_in[3],
                         (const float*)d_in[5], (const float*)d_in[7]};
    const float* bi[4] = {(const float*)d_in[2], (const float*)d_in[4],
                          (const float*)d_in[6], (const float*)d_in[8]};
    float* out = (float*)d_out;

    float *qb, *kb, *vb, *ab;
    cudaGetSymbolAddress((void**)&qb, g_Q);
    cudaGetSymbolAddress((void**)&kb, g_K);
    cudaGetSymbolAddress((void**)&vb, g_V);
    cudaGetSymbolAddress((void**)&ab, g_AO);
    __nv_bfloat16 *xh, *xl, *wh, *wl, *ah, *al, *qh, *ql, *kh, *kl, *vth, *vtl;
    cudaGetSymbolAddress((void**)&xh, g_xhi);  cudaGetSymbolAddress((void**)&xl, g_xlo);
    cudaGetSymbolAddress((void**)&wh, g_whi);  cudaGetSymbolAddress((void**)&wl, g_wlo);
    cudaGetSymbolAddress((void**)&ah, g_ahi);  cudaGetSymbolAddress((void**)&al, g_alo);
    cudaGetSymbolAddress((void**)&qh, g_qhi);  cudaGetSymbolAddress((void**)&ql, g_qlo);
    cudaGetSymbolAddress((void**)&kh, g_khi);  cudaGetSymbolAddress((void**)&kl, g_klo);
    cudaGetSymbolAddress((void**)&vth, g_vthi); cudaGetSymbolAddress((void**)&vtl, g_vtlo);

    const size_t WN = (size_t)DMODEL * DMODEL;
    const int ECNT = ROWS * DMODEL / 1024;
    convert_split<<<ECNT, 256>>>(x, xh, xl);
    for (int i = 0; i < 4; i++)
        convert_split<<<WN / 1024, 256>>>(w[i], wh + i * WN, wl + i * WN);

    size_t gsmem = 2 * STGE * sizeof(__nv_bfloat16);
    cudaFuncSetAttribute(gemm_bf16x3, cudaFuncAttributeMaxDynamicSharedMemorySize,
                         (int)gsmem);
    dim3 ggrid(DMODEL / 128, ROWS / 128);
    gemm_bf16x3<<<ggrid, 256, gsmem>>>(xh, xl, wh + 0 * WN, wl + 0 * WN, bi[0], qb);
    gemm_bf16x3<<<ggrid, 256, gsmem>>>(xh, xl, wh + 1 * WN, wl + 1 * WN, bi[1], kb);
    gemm_bf16x3<<<ggrid, 256, gsmem>>>(xh, xl, wh + 2 * WN, wl + 2 * WN, bi[2], vb);

    int pairs = ROWS * NHEADS * (DK / 2);
    rope_kernel<<<(pairs + 255) / 256, 256>>>(qb, 0.08838834764831843f);
    rope_kernel<<<(pairs + 255) / 256, 256>>>(kb, 1.0f);

    convert_split<<<ECNT, 256>>>(qb, qh, ql);
    convert_split<<<ECNT, 256>>>(kb, kh, kl);
    dim3 vgrid(SEQ / 32, DK / 32, BATCH * NHEADS);
    convert_vt<<<vgrid, 256>>>(vb, vth, vtl);

    size_t fsmem = FTOT * sizeof(__nv_bfloat16);
    cudaFuncSetAttribute(flash_mma, cudaFuncAttributeMaxDynamicSharedMemorySize,
                         (int)fsmem);
    dim3 fgrid(SEQ / 64, BATCH * NHEADS);
    flash_mma<<<fgrid, 128, fsmem>>>(qh, ql, kh, kl, vth, vtl, ab);

    convert_split<<<ECNT, 256>>>(ab, ah, al);
    gemm_bf16x3<<<ggrid, 256, gsmem>>>(ah, al, wh + 3 * WN, wl + 3 * WN, bi[3], out);
}

// round 6
// speedup vs baseline: 2.5878x; 1.1223x over previous
#include <cuda_runtime.h>
#include <cuda_bf16.h>
#include <math.h>
#include <stdint.h>

#define BATCH   2
#define SEQ     2048
#define DMODEL  2048
#define NHEADS  16
#define DK      128
#define ROWS    (BATCH * SEQ)

// ---------------- scratch ----------------------------------------------------
__device__ float g_Q[ROWS * DMODEL];
__device__ float g_K[ROWS * DMODEL];
__device__ float g_V[ROWS * DMODEL];
__device__ float g_AO[ROWS * DMODEL];
__device__ __nv_bfloat16 g_xhi[ROWS * DMODEL],    g_xlo[ROWS * DMODEL];
__device__ __nv_bfloat16 g_whi[4][DMODEL * DMODEL], g_wlo[4][DMODEL * DMODEL];
__device__ __nv_bfloat16 g_ahi[ROWS * DMODEL],    g_alo[ROWS * DMODEL];
__device__ __nv_bfloat16 g_qhi[ROWS * DMODEL],    g_qlo[ROWS * DMODEL];
__device__ __nv_bfloat16 g_khi[ROWS * DMODEL],    g_klo[ROWS * DMODEL];
__device__ __nv_bfloat16 g_vthi[ROWS * DMODEL],   g_vtlo[ROWS * DMODEL];

// ---------------- helpers ----------------------------------------------------
__device__ __forceinline__ uint32_t smem_u32(const void* p) {
    return (uint32_t)__cvta_generic_to_shared(p);
}
__device__ __forceinline__ void ldmx4(uint32_t& r0, uint32_t& r1, uint32_t& r2,
                                      uint32_t& r3, uint32_t a) {
    asm volatile("ldmatrix.sync.aligned.m8n8.x4.shared.b16 {%0,%1,%2,%3},[%4];"
                 : "=r"(r0), "=r"(r1), "=r"(r2), "=r"(r3) : "r"(a));
}
__device__ __forceinline__ void mma_bf(float* c, uint32_t a0, uint32_t a1,
                                       uint32_t a2, uint32_t a3,
                                       uint32_t b0, uint32_t b1) {
    asm volatile(
        "mma.sync.aligned.m16n8k16.row.col.f32.bf16.bf16.f32 "
        "{%0,%1,%2,%3},{%4,%5,%6,%7},{%8,%9},{%0,%1,%2,%3};"
        : "+f"(c[0]), "+f"(c[1]), "+f"(c[2]), "+f"(c[3])
        : "r"(a0), "r"(a1), "r"(a2), "r"(a3), "r"(b0), "r"(b1));
}
__device__ __forceinline__ void cpasync16(uint32_t dst, const void* src) {
    asm volatile("cp.async.cg.shared.global [%0],[%1],16;" :: "r"(dst), "l"(src));
}
#define CP_COMMIT asm volatile("cp.async.commit_group;")
template<int N> __device__ __forceinline__ void cp_wait() {
    asm volatile("cp.async.wait_group %0;" :: "n"(N));
}
__device__ __forceinline__ void split2(float v, __nv_bfloat16& h, __nv_bfloat16& l) {
    h = __float2bfloat16(v);
    l = __float2bfloat16(v - __bfloat162float(h));
}
__device__ __forceinline__ void splitpack(float x, float y, uint32_t& h, uint32_t& l) {
    __nv_bfloat162 hh, ll;
    split2(x, hh.x, ll.x); split2(y, hh.y, ll.y);
    h = *(uint32_t*)&hh; l = *(uint32_t*)&ll;
}

// ---------------- convert fp32 -> hi/lo bf16 planes --------------------------
__global__ __launch_bounds__(256)
void convert_split(const float* __restrict__ in, __nv_bfloat16* __restrict__ hi,
                   __nv_bfloat16* __restrict__ lo)
{
    int i = (blockIdx.x * blockDim.x + threadIdx.x) * 4;
    float4 v = *(const float4*)(in + i);
    __nv_bfloat162 h0, h1, l0, l1;
    split2(v.x, h0.x, l0.x); split2(v.y, h0.y, l0.y);
    split2(v.z, h1.x, l1.x); split2(v.w, h1.y, l1.y);
    *(__nv_bfloat162*)&hi[i]     = h0;  *(__nv_bfloat162*)&hi[i + 2] = h1;
    *(__nv_bfloat162*)&lo[i]     = l0;  *(__nv_bfloat162*)&lo[i + 2] = l1;
}

// ---------------- V -> transposed per-head planes [bh][d][s] -----------------
__global__ __launch_bounds__(256)
void convert_vt(const float* __restrict__ V, __nv_bfloat16* __restrict__ hi,
                __nv_bfloat16* __restrict__ lo)
{
    __shared__ float t[32][33];
    int bh = blockIdx.z, b = bh >> 4, h = bh & 15;
    int s0 = blockIdx.x * 32, d0 = blockIdx.y * 32;
    int lx = threadIdx.x & 31, ly = threadIdx.x >> 5;
#pragma unroll
    for (int i = 0; i < 4; i++) {
        int sl = ly + i * 8;
        t[sl][lx] = V[(size_t)(b * SEQ + s0 + sl) * DMODEL + h * DK + d0 + lx];
    }
    __syncthreads();
#pragma unroll
    for (int i = 0; i < 4; i++) {
        int dl = ly + i * 8;
        __nv_bfloat16 hh, ll; split2(t[lx][dl], hh, ll);
        size_t o = (size_t)(bh * DK + d0 + dl) * SEQ + s0 + lx;
        hi[o] = hh; lo[o] = ll;
    }
}

// ---------------- bf16x3 GEMM: C = A @ B^T + bias (fp32 out) -----------------
// 128x128x32 tiles, 8 warps, 2-stage cp.async, ONE sync per stage, occ 2.
#define NKIT (DMODEL / 32)
#define PLE  (128 * 40)
#define STGE (4 * PLE)

__global__ __launch_bounds__(256, 2)
void gemm_bf16x3(const __nv_bfloat16* __restrict__ Ahi, const __nv_bfloat16* __restrict__ Alo,
                 const __nv_bfloat16* __restrict__ Bhi, const __nv_bfloat16* __restrict__ Blo,
                 const float* __restrict__ bias, float* __restrict__ C)
{
    extern __shared__ __nv_bfloat16 sm[];
    const int tid = threadIdx.x, lane = tid & 31, wid = tid >> 5;
    const int wm = wid & 3, wn = wid >> 2;
    const int m0 = blockIdx.y * 128, n0 = blockIdx.x * 128;
    const uint32_t sb = smem_u32(sm);
    const __nv_bfloat16* srcs[4] = {Ahi, Alo, Bhi, Blo};

    auto issue = [&](int kt, int stg) {
        int kofs = kt * 32;
#pragma unroll
        for (int i = 0; i < 8; i++) {
            int idx = tid + i * 256;
            int plane = idx >> 9, rem = idx & 511;
            int row = rem >> 2, ch = (rem & 3) * 8;
            int grow = (plane < 2 ? m0 : n0) + row;
            cpasync16(sb + (stg * STGE + plane * PLE + row * 40 + ch) * 2,
                      srcs[plane] + (size_t)grow * DMODEL + kofs + ch);
        }
    };

    float acc[2][8][4];
#pragma unroll
    for (int a = 0; a < 2; a++)
#pragma unroll
        for (int b = 0; b < 8; b++)
#pragma unroll
            for (int c = 0; c < 4; c++) acc[a][b][c] = 0.f;

    issue(0, 0); CP_COMMIT;

    for (int kt = 0; kt < NKIT; kt++) {
        cp_wait<0>();          // stage kt resident
        __syncthreads();       // also guarantees buffer (kt+1)&1 is free
        if (kt + 1 < NKIT) { issue(kt + 1, (kt + 1) & 1); CP_COMMIT; }
        uint32_t s0 = sb + ((kt & 1) * STGE) * 2;

#pragma unroll
        for (int ks = 0; ks < 32; ks += 16) {
            uint32_t ah[2][4], al[2][4];
#pragma unroll
            for (int mt = 0; mt < 2; mt++) {
                int ar = wm * 32 + mt * 16 + (lane & 15);
                int ac = ks + ((lane >> 4) << 3);
                uint32_t off = (uint32_t)(ar * 40 + ac) * 2;
                ldmx4(ah[mt][0], ah[mt][1], ah[mt][2], ah[mt][3], s0 + off);
                ldmx4(al[mt][0], al[mt][1], al[mt][2], al[mt][3], s0 + PLE * 2 + off);
            }
#pragma unroll
            for (int np = 0; np < 4; np++) {
                int br = wn * 64 + np * 16 + ((lane >> 4) << 3) + (lane & 7);
                int bc = ks + (((lane >> 3) & 1) << 3);
                uint32_t off = (uint32_t)(br * 40 + bc) * 2;
                uint32_t h0, h1, h2, h3, q0, q1, q2, q3;
                ldmx4(h0, h1, h2, h3, s0 + PLE * 4 + off);
                ldmx4(q0, q1, q2, q3, s0 + PLE * 6 + off);
#pragma unroll
                for (int mt = 0; mt < 2; mt++) {
                    float* c0 = acc[mt][2 * np];
                    float* c1 = acc[mt][2 * np + 1];
                    mma_bf(c0, ah[mt][0], ah[mt][1], ah[mt][2], ah[mt][3], h0, h1);
                    mma_bf(c0, ah[mt][0], ah[mt][1], ah[mt][2], ah[mt][3], q0, q1);
                    mma_bf(c0, al[mt][0], al[mt][1], al[mt][2], al[mt][3], h0, h1);
                    mma_bf(c1, ah[mt][0], ah[mt][1], ah[mt][2], ah[mt][3], h2, h3);
                    mma_bf(c1, ah[mt][0], ah[mt][1], ah[mt][2], ah[mt][3], q2, q3);
                    mma_bf(c1, al[mt][0], al[mt][1], al[mt][2], al[mt][3], h2, h3);
                }
            }
        }
        __syncthreads();       // compute done before next wait can recycle buffer
    }

#pragma unroll
    for (int mt = 0; mt < 2; mt++) {
        int r = m0 + wm * 32 + mt * 16 + (lane >> 2);
#pragma unroll
        for (int nt = 0; nt < 8; nt++) {
            int gc = n0 + wn * 64 + nt * 8 + (lane & 3) * 2;
            float b0 = bias[gc], b1 = bias[gc + 1];
            float2 v0 = {acc[mt][nt][0] + b0, acc[mt][nt][1] + b1};
            float2 v1 = {acc[mt][nt][2] + b0, acc[mt][nt][3] + b1};
            *(float2*)&C[(size_t)r * DMODEL + gc] = v0;
            *(float2*)&C[(size_t)(r + 8) * DMODEL + gc] = v1;
        }
    }
}

// ---------------- RoPE ------------------------------------------------------
__global__ __launch_bounds__(256)
void rope_kernel(float* __restrict__ buf, float outscale)
{
    int idx = blockIdx.x * blockDim.x + threadIdx.x;
    if (idx >= ROWS * NHEADS * (DK / 2)) return;
    int i = idx & 63, h = (idx >> 6) & 15, row = idx >> 10, s = row & (SEQ - 1);
    float inv_freq = powf(10000.0f, -((float)(2 * i)) / 128.0f);
    float fr = (float)s * inv_freq, c, sn;
    sincosf(fr, &sn, &c);
    float* p = buf + (size_t)row * DMODEL + h * DK + 2 * i;
    float e = p[0], o = p[1];
    p[0] = (e * c - o * sn) * outscale;
    p[1] = (e * sn + o * c) * outscale;
}

// ---------------- Flash attention on mma.sync (passing round-4 version) ------
#define FQH 0
#define FQL 8704
#define FKH 17408
#define FKL 26112
#define FVH 34816
#define FVL 44032
#define FTOT 53248

__global__ __launch_bounds__(128, 2)
void flash_mma(const __nv_bfloat16* __restrict__ Qh, const __nv_bfloat16* __restrict__ Ql,
               const __nv_bfloat16* __restrict__ Kh, const __nv_bfloat16* __restrict__ Kl,
               const __nv_bfloat16* __restrict__ Vh, const __nv_bfloat16* __restrict__ Vl,
               float* __restrict__ O)
{
    extern __shared__ __nv_bfloat16 sm[];
    const uint32_t sb = smem_u32(sm);
    const int tid = threadIdx.x, lane = tid & 31, warp = tid >> 5;
    const int qblk = blockIdx.x, bh = blockIdx.y;
    const int b = bh >> 4, h = bh & 15, q0 = qblk * 64;
    const int hofs = h * DK;
    const size_t qrow0 = (size_t)(b * SEQ + q0);
    const __nv_bfloat16* vtbase_h = Vh + (size_t)bh * DK * SEQ;
    const __nv_bfloat16* vtbase_l = Vl + (size_t)bh * DK * SEQ;

#pragma unroll
    for (int i = 0; i < 8; i++) {
        int idx = tid + i * 128;
        int r = idx >> 4, c = (idx & 15) * 8;
        cpasync16(sb + (FQH + r * 136 + c) * 2, Qh + (qrow0 + r) * DMODEL + hofs + c);
        cpasync16(sb + (FQL + r * 136 + c) * 2, Ql + (qrow0 + r) * DMODEL + hofs + c);
    }
    CP_COMMIT;

    float o[16][4];
#pragma unroll
    for (int t = 0; t < 16; t++)
#pragma unroll
        for (int e = 0; e < 4; e++) o[t][e] = 0.f;
    float m0v = -INFINITY, m1v = -INFINITY, l0v = 0.f, l1v = 0.f;

    for (int jb = 0; jb <= qblk; ++jb) {
        const int k0 = jb * 64;
        const size_t krow0 = (size_t)(b * SEQ + k0);
#pragma unroll
        for (int i = 0; i < 8; i++) {
            int idx = tid + i * 128;
            int r = idx >> 4, c = (idx & 15) * 8;
            cpasync16(sb + (FKH + r * 136 + c) * 2, Kh + (krow0 + r) * DMODEL + hofs + c);
            cpasync16(sb + (FKL + r * 136 + c) * 2, Kl + (krow0 + r) * DMODEL + hofs + c);
        }
#pragma unroll
        for (int i = 0; i < 8; i++) {
            int idx = tid + i * 128;
            int d = idx >> 3, c = (idx & 7) * 8;
            cpasync16(sb + (FVH + d * 72 + c) * 2, vtbase_h + (size_t)d * SEQ + k0 + c);
            cpasync16(sb + (FVL + d * 72 + c) * 2, vtbase_l + (size_t)d * SEQ + k0 + c);
        }
        CP_COMMIT; cp_wait<0>();
        __syncthreads();

        float s[8][4];
#pragma unroll
        for (int t = 0; t < 8; t++)
#pragma unroll
            for (int e = 0; e < 4; e++) s[t][e] = 0.f;

#pragma unroll
        for (int kc = 0; kc < 8; kc++) {
            int ar = warp * 16 + (lane & 15);
            int ac = kc * 16 + ((lane >> 4) << 3);
            uint32_t aoff = (uint32_t)(ar * 136 + ac) * 2;
            uint32_t qh0, qh1, qh2, qh3, ql0, ql1, ql2, ql3;
            ldmx4(qh0, qh1, qh2, qh3, sb + FQH * 2 + aoff);
            ldmx4(ql0, ql1, ql2, ql3, sb + FQL * 2 + aoff);
#pragma unroll
            for (int np = 0; np < 4; np++) {
                int br = np * 16 + ((lane >> 4) << 3) + (lane & 7);
                int bc = kc * 16 + (((lane >> 3) & 1) << 3);
                uint32_t boff = (uint32_t)(br * 136 + bc) * 2;
                uint32_t kh0, kh1, kh2, kh3, kl0, kl1, kl2, kl3;
                ldmx4(kh0, kh1, kh2, kh3, sb + FKH * 2 + boff);
                ldmx4(kl0, kl1, kl2, kl3, sb + FKL * 2 + boff);
                mma_bf(s[2 * np],     qh0, qh1, qh2, qh3, kh0, kh1);
                mma_bf(s[2 * np],     ql0, ql1, ql2, ql3, kh0, kh1);
                mma_bf(s[2 * np],     qh0, qh1, qh2, qh3, kl0, kl1);
                mma_bf(s[2 * np + 1], qh0, qh1, qh2, qh3, kh2, kh3);
                mma_bf(s[2 * np + 1], ql0, ql1, ql2, ql3, kh2, kh3);
                mma_bf(s[2 * np + 1], qh0, qh1, qh2, qh3, kl2, kl3);
            }
        }

        if (jb == qblk) {
            int r0 = q0 + warp * 16 + (lane >> 2);
#pragma unroll
            for (int t = 0; t < 8; t++) {
                int c0 = k0 + t * 8 + 2 * (lane & 3);
                if (c0 > r0)     s[t][0] = -INFINITY;
                if (c0 + 1 > r0) s[t][1] = -INFINITY;
                if (c0 > r0 + 8)     s[t][2] = -INFINITY;
                if (c0 + 1 > r0 + 8) s[t][3] = -INFINITY;
            }
        }

        float mx0 = -INFINITY, mx1 = -INFINITY;
#pragma unroll
        for (int t = 0; t < 8; t++) {
            mx0 = fmaxf(mx0, fmaxf(s[t][0], s[t][1]));
            mx1 = fmaxf(mx1, fmaxf(s[t][2], s[t][3]));
        }
        mx0 = fmaxf(mx0, __shfl_xor_sync(0xffffffffu, mx0, 1));
        mx0 = fmaxf(mx0, __shfl_xor_sync(0xffffffffu, mx0, 2));
        mx1 = fmaxf(mx1, __shfl_xor_sync(0xffffffffu, mx1, 1));
        mx1 = fmaxf(mx1, __shfl_xor_sync(0xffffffffu, mx1, 2));
        float mn0 = fmaxf(m0v, mx0), mn1 = fmaxf(m1v, mx1);
        float sc0 = __expf(m0v - mn0), sc1 = __expf(m1v - mn1);
        float sum0 = 0.f, sum1 = 0.f;
#pragma unroll
        for (int t = 0; t < 8; t++) {
            s[t][0] = __expf(s[t][0] - mn0); sum0 += s[t][0];
            s[t][1] = __expf(s[t][1] - mn0); sum0 += s[t][1];
            s[t][2] = __expf(s[t][2] - mn1); sum1 += s[t][2];
            s[t][3] = __expf(s[t][3] - mn1); sum1 += s[t][3];
        }
        sum0 += __shfl_xor_sync(0xffffffffu, sum0, 1);
        sum0 += __shfl_xor_sync(0xffffffffu, sum0, 2);
        sum1 += __shfl_xor_sync(0xffffffffu, sum1, 1);
        sum1 += __shfl_xor_sync(0xffffffffu, sum1, 2);
        l0v = l0v * sc0 + sum0; m0v = mn0;
        l1v = l1v * sc1 + sum1; m1v = mn1;

#pragma unroll
        for (int t = 0; t < 16; t++) {
            o[t][0] *= sc0; o[t][1] *= sc0; o[t][2] *= sc1; o[t][3] *= sc1;
        }

#pragma unroll
        for (int kc = 0; kc < 4; kc++) {
            uint32_t ah0, ah1, ah2, ah3, al0, al1, al2, al3;
            splitpack(s[2 * kc][0],     s[2 * kc][1],     ah0, al0);
            splitpack(s[2 * kc][2],     s[2 * kc][3],     ah1, al1);
            splitpack(s[2 * kc + 1][0], s[2 * kc + 1][1], ah2, al2);
            splitpack(s[2 * kc + 1][2], s[2 * kc + 1][3], ah3, al3);
#pragma unroll
            for (int np = 0; np < 8; np++) {
                int br = np * 16 + ((lane >> 4) << 3) + (lane & 7);
                int bc = kc * 16 + (((lane >> 3) & 1) << 3);
                uint32_t boff = (uint32_t)(br * 72 + bc) * 2;
                uint32_t vh0, vh1, vh2, vh3, vl0, vl1, vl2, vl3;
                ldmx4(vh0, vh1, vh2, vh3, sb + FVH * 2 + boff);
                ldmx4(vl0, vl1, vl2, vl3, sb + FVL * 2 + boff);
                mma_bf(o[2 * np],     ah0, ah1, ah2, ah3, vh0, vh1);
                mma_bf(o[2 * np],     al0, al1, al2, al3, vh0, vh1);
                mma_bf(o[2 * np],     ah0, ah1, ah2, ah3, vl0, vl1);
                mma_bf(o[2 * np + 1], ah0, ah1, ah2, ah3, vh2, vh3);
                mma_bf(o[2 * np + 1], al0, al1, al2, al3, vh2, vh3);
                mma_bf(o[2 * np + 1], ah0, ah1, ah2, ah3, vl2, vl3);
            }
        }
        __syncthreads();
    }

    float inv0 = 1.f / l0v, inv1 = 1.f / l1v;
    int r0 = b * SEQ + q0 + warp * 16 + (lane >> 2);
#pragma unroll
    for (int t = 0; t < 16; t++) {
        int gc = hofs + t * 8 + 2 * (lane & 3);
        float2 v0 = {o[t][0] * inv0, o[t][1] * inv0};
        float2 v1 = {o[t][2] * inv1, o[t][3] * inv1};
        *(float2*)&O[(size_t)r0 * DMODEL + gc] = v0;
        *(float2*)&O[(size_t)(r0 + 8) * DMODEL + gc] = v1;
    }
}

// ---------------- launch ------------------------------------------------------
extern "C" void kernel_launch(void* const* d_in, const int* in_sizes, int n_in,
                              void* d_out, int out_size)
{
    const float* x    = (const float*)d_in[0];
    const float* w[4] = {(const float*)d_in[1], (const float*)d_in[3],
                         (const float*)d_in[5], (const float*)d_in[7]};
    const float* bi[4] = {(const float*)d_in[2], (const float*)d_in[4],
                          (const float*)d_in[6], (const float*)d_in[8]};
    float* out = (float*)d_out;

    float *qb, *kb, *vb, *ab;
    cudaGetSymbolAddress((void**)&qb, g_Q);
    cudaGetSymbolAddress((void**)&kb, g_K);
    cudaGetSymbolAddress((void**)&vb, g_V);
    cudaGetSymbolAddress((void**)&ab, g_AO);
    __nv_bfloat16 *xh, *xl, *wh, *wl, *ah, *al, *qh, *ql, *kh, *kl, *vth, *vtl;
    cudaGetSymbolAddress((void**)&xh, g_xhi);  cudaGetSymbolAddress((void**)&xl, g_xlo);
    cudaGetSymbolAddress((void**)&wh, g_whi);  cudaGetSymbolAddress((void**)&wl, g_wlo);
    cudaGetSymbolAddress((void**)&ah, g_ahi);  cudaGetSymbolAddress((void**)&al, g_alo);
    cudaGetSymbolAddress((void**)&qh, g_qhi);  cudaGetSymbolAddress((void**)&ql, g_qlo);
    cudaGetSymbolAddress((void**)&kh, g_khi);  cudaGetSymbolAddress((void**)&kl, g_klo);
    cudaGetSymbolAddress((void**)&vth, g_vthi); cudaGetSymbolAddress((void**)&vtl, g_vtlo);

    const size_t WN = (size_t)DMODEL * DMODEL;
    const int ECNT = ROWS * DMODEL / 1024;
    convert_split<<<ECNT, 256>>>(x, xh, xl);
    for (int i = 0; i < 4; i++)
        convert_split<<<WN / 1024, 256>>>(w[i], wh + i * WN, wl + i * WN);

    size_t gsmem = 2 * STGE * sizeof(__nv_bfloat16);
    cudaFuncSetAttribute(gemm_bf16x3, cudaFuncAttributeMaxDynamicSharedMemorySize,
                         (int)gsmem);
    dim3 ggrid(DMODEL / 128, ROWS / 128);
    gemm_bf16x3<<<ggrid, 256, gsmem>>>(xh, xl, wh + 0 * WN, wl + 0 * WN, bi[0], qb);
    gemm_bf16x3<<<ggrid, 256, gsmem>>>(xh, xl, wh + 1 * WN, wl + 1 * WN, bi[1], kb);
    gemm_bf16x3<<<ggrid, 256, gsmem>>>(xh, xl, wh + 2 * WN, wl + 2 * WN, bi[2], vb);

    int pairs = ROWS * NHEADS * (DK / 2);
    rope_kernel<<<(pairs + 255) / 256, 256>>>(qb, 0.08838834764831843f);
    rope_kernel<<<(pairs + 255) / 256, 256>>>(kb, 1.0f);

    convert_split<<<ECNT, 256>>>(qb, qh, ql);
    convert_split<<<ECNT, 256>>>(kb, kh, kl);
    dim3 vgrid(SEQ / 32, DK / 32, BATCH * NHEADS);
    convert_vt<<<vgrid, 256>>>(vb, vth, vtl);

    size_t fsmem = FTOT * sizeof(__nv_bfloat16);
    cudaFuncSetAttribute(flash_mma, cudaFuncAttributeMaxDynamicSharedMemorySize,
                         (int)fsmem);
    dim3 fgrid(SEQ / 64, BATCH * NHEADS);
    flash_mma<<<fgrid, 128, fsmem>>>(qh, ql, kh, kl, vth, vtl, ab);

    convert_split<<<ECNT, 256>>>(ab, ah, al);
    gemm_bf16x3<<<ggrid, 256, gsmem>>>(ah, al, wh + 3 * WN, wl + 3 * WN, bi[3], out);
}

// round 7
// speedup vs baseline: 2.6689x; 1.0313x over previous
#include <cuda_runtime.h>
#include <cuda_bf16.h>
#include <math.h>
#include <stdint.h>

#define BATCH   2
#define SEQ     2048
#define DMODEL  2048
#define NHEADS  16
#define DK      128
#define ROWS    (BATCH * SEQ)

// ---------------- scratch ----------------------------------------------------
__device__ float g_V[ROWS * DMODEL];
__device__ __nv_bfloat16 g_xhi[ROWS * DMODEL],    g_xlo[ROWS * DMODEL];
__device__ __nv_bfloat16 g_whi[4][DMODEL * DMODEL], g_wlo[4][DMODEL * DMODEL];
__device__ __nv_bfloat16 g_ahi[ROWS * DMODEL],    g_alo[ROWS * DMODEL];
__device__ __nv_bfloat16 g_qhi[ROWS * DMODEL],    g_qlo[ROWS * DMODEL];
__device__ __nv_bfloat16 g_khi[ROWS * DMODEL],    g_klo[ROWS * DMODEL];
__device__ __nv_bfloat16 g_vthi[ROWS * DMODEL],   g_vtlo[ROWS * DMODEL];

// ---------------- helpers ----------------------------------------------------
__device__ __forceinline__ uint32_t smem_u32(const void* p) {
    return (uint32_t)__cvta_generic_to_shared(p);
}
__device__ __forceinline__ void ldmx4(uint32_t& r0, uint32_t& r1, uint32_t& r2,
                                      uint32_t& r3, uint32_t a) {
    asm volatile("ldmatrix.sync.aligned.m8n8.x4.shared.b16 {%0,%1,%2,%3},[%4];"
                 : "=r"(r0), "=r"(r1), "=r"(r2), "=r"(r3) : "r"(a));
}
__device__ __forceinline__ void mma_bf(float* c, uint32_t a0, uint32_t a1,
                                       uint32_t a2, uint32_t a3,
                                       uint32_t b0, uint32_t b1) {
    asm volatile(
        "mma.sync.aligned.m16n8k16.row.col.f32.bf16.bf16.f32 "
        "{%0,%1,%2,%3},{%4,%5,%6,%7},{%8,%9},{%0,%1,%2,%3};"
        : "+f"(c[0]), "+f"(c[1]), "+f"(c[2]), "+f"(c[3])
        : "r"(a0), "r"(a1), "r"(a2), "r"(a3), "r"(b0), "r"(b1));
}
__device__ __forceinline__ void cpasync16(uint32_t dst, const void* src) {
    asm volatile("cp.async.cg.shared.global [%0],[%1],16;" :: "r"(dst), "l"(src));
}
#define CP_COMMIT asm volatile("cp.async.commit_group;")
template<int N> __device__ __forceinline__ void cp_wait() {
    asm volatile("cp.async.wait_group %0;" :: "n"(N));
}
__device__ __forceinline__ void split2(float v, __nv_bfloat16& h, __nv_bfloat16& l) {
    h = __float2bfloat16(v);
    l = __float2bfloat16(v - __bfloat162float(h));
}
__device__ __forceinline__ void splitpack(float x, float y, uint32_t& h, uint32_t& l) {
    __nv_bfloat162 hh, ll;
    split2(x, hh.x, ll.x); split2(y, hh.y, ll.y);
    h = *(uint32_t*)&hh; l = *(uint32_t*)&ll;
}

// ---------------- convert fp32 -> hi/lo bf16 planes --------------------------
__global__ __launch_bounds__(256)
void convert_split(const float* __restrict__ in, __nv_bfloat16* __restrict__ hi,
                   __nv_bfloat16* __restrict__ lo)
{
    int i = (blockIdx.x * blockDim.x + threadIdx.x) * 4;
    float4 v = *(const float4*)(in + i);
    __nv_bfloat162 h0, h1, l0, l1;
    split2(v.x, h0.x, l0.x); split2(v.y, h0.y, l0.y);
    split2(v.z, h1.x, l1.x); split2(v.w, h1.y, l1.y);
    *(__nv_bfloat162*)&hi[i]     = h0;  *(__nv_bfloat162*)&hi[i + 2] = h1;
    *(__nv_bfloat162*)&lo[i]     = l0;  *(__nv_bfloat162*)&lo[i + 2] = l1;
}

// ---------------- V -> transposed per-head planes [bh][d][s] -----------------
__global__ __launch_bounds__(256)
void convert_vt(const float* __restrict__ V, __nv_bfloat16* __restrict__ hi,
                __nv_bfloat16* __restrict__ lo)
{
    __shared__ float t[32][33];
    int bh = blockIdx.z, b = bh >> 4, h = bh & 15;
    int s0 = blockIdx.x * 32, d0 = blockIdx.y * 32;
    int lx = threadIdx.x & 31, ly = threadIdx.x >> 5;
#pragma unroll
    for (int i = 0; i < 4; i++) {
        int sl = ly + i * 8;
        t[sl][lx] = V[(size_t)(b * SEQ + s0 + sl) * DMODEL + h * DK + d0 + lx];
    }
    __syncthreads();
#pragma unroll
    for (int i = 0; i < 4; i++) {
        int dl = ly + i * 8;
        __nv_bfloat16 hh, ll; split2(t[lx][dl], hh, ll);
        size_t o = (size_t)(bh * DK + d0 + dl) * SEQ + s0 + lx;
        hi[o] = hh; lo[o] = ll;
    }
}

// ---------------- bf16x3 GEMM: C = A @ B^T + bias ----------------------------
// MODE 0: fp32 out. MODE 1: fused RoPE (per-head pairs) + hi/lo plane out.
#define NKIT (DMODEL / 32)
#define PLE  (128 * 40)
#define STGE (4 * PLE)

template<int MODE>
__global__ __launch_bounds__(256, 2)
void gemm_bf16x3(const __nv_bfloat16* __restrict__ Ahi, const __nv_bfloat16* __restrict__ Alo,
                 const __nv_bfloat16* __restrict__ Bhi, const __nv_bfloat16* __restrict__ Blo,
                 const float* __restrict__ bias, float* __restrict__ Cf,
                 __nv_bfloat16* __restrict__ Chi, __nv_bfloat16* __restrict__ Clo,
                 float ropescale)
{
    extern __shared__ __nv_bfloat16 sm[];
    const int tid = threadIdx.x, lane = tid & 31, wid = tid >> 5;
    const int wm = wid & 3, wn = wid >> 2;
    const int m0 = blockIdx.y * 128, n0 = blockIdx.x * 128;
    const uint32_t sb = smem_u32(sm);
    const __nv_bfloat16* srcs[4] = {Ahi, Alo, Bhi, Blo};

    auto issue = [&](int kt, int stg) {
        int kofs = kt * 32;
#pragma unroll
        for (int i = 0; i < 8; i++) {
            int idx = tid + i * 256;
            int plane = idx >> 9, rem = idx & 511;
            int row = rem >> 2, ch = (rem & 3) * 8;
            int grow = (plane < 2 ? m0 : n0) + row;
            cpasync16(sb + (stg * STGE + plane * PLE + row * 40 + ch) * 2,
                      srcs[plane] + (size_t)grow * DMODEL + kofs + ch);
        }
    };

    float acc[2][8][4];
#pragma unroll
    for (int a = 0; a < 2; a++)
#pragma unroll
        for (int b = 0; b < 8; b++)
#pragma unroll
            for (int c = 0; c < 4; c++) acc[a][b][c] = 0.f;

    issue(0, 0); CP_COMMIT;

    for (int kt = 0; kt < NKIT; kt++) {
        cp_wait<0>();
        __syncthreads();
        if (kt + 1 < NKIT) { issue(kt + 1, (kt + 1) & 1); CP_COMMIT; }
        uint32_t s0 = sb + ((kt & 1) * STGE) * 2;

#pragma unroll
        for (int ks = 0; ks < 32; ks += 16) {
            uint32_t ah[2][4], al[2][4];
#pragma unroll
            for (int mt = 0; mt < 2; mt++) {
                int ar = wm * 32 + mt * 16 + (lane & 15);
                int ac = ks + ((lane >> 4) << 3);
                uint32_t off = (uint32_t)(ar * 40 + ac) * 2;
                ldmx4(ah[mt][0], ah[mt][1], ah[mt][2], ah[mt][3], s0 + off);
                ldmx4(al[mt][0], al[mt][1], al[mt][2], al[mt][3], s0 + PLE * 2 + off);
            }
#pragma unroll
            for (int np = 0; np < 4; np++) {
                int br = wn * 64 + np * 16 + ((lane >> 4) << 3) + (lane & 7);
                int bc = ks + (((lane >> 3) & 1) << 3);
                uint32_t off = (uint32_t)(br * 40 + bc) * 2;
                uint32_t h0, h1, h2, h3, q0, q1, q2, q3;
                ldmx4(h0, h1, h2, h3, s0 + PLE * 4 + off);
                ldmx4(q0, q1, q2, q3, s0 + PLE * 6 + off);
#pragma unroll
                for (int mt = 0; mt < 2; mt++) {
                    float* c0 = acc[mt][2 * np];
                    float* c1 = acc[mt][2 * np + 1];
                    mma_bf(c0, ah[mt][0], ah[mt][1], ah[mt][2], ah[mt][3], h0, h1);
                    mma_bf(c0, ah[mt][0], ah[mt][1], ah[mt][2], ah[mt][3], q0, q1);
                    mma_bf(c0, al[mt][0], al[mt][1], al[mt][2], al[mt][3], h0, h1);
                    mma_bf(c1, ah[mt][0], ah[mt][1], ah[mt][2], ah[mt][3], h2, h3);
                    mma_bf(c1, ah[mt][0], ah[mt][1], ah[mt][2], ah[mt][3], q2, q3);
                    mma_bf(c1, al[mt][0], al[mt][1], al[mt][2], al[mt][3], h2, h3);
                }
            }
        }
        __syncthreads();
    }

#pragma unroll
    for (int mt = 0; mt < 2; mt++) {
        int r = m0 + wm * 32 + mt * 16 + (lane >> 2);
        int s_pos0 = r & (SEQ - 1);
#pragma unroll
        for (int nt = 0; nt < 8; nt++) {
            int gc = n0 + wn * 64 + nt * 8 + (lane & 3) * 2;
            float b0 = bias[gc], b1 = bias[gc + 1];
            float e0 = acc[mt][nt][0] + b0, o0 = acc[mt][nt][1] + b1;
            float e1 = acc[mt][nt][2] + b0, o1 = acc[mt][nt][3] + b1;
            if (MODE == 0) {
                float2 v0 = {e0, o0}, v1 = {e1, o1};
                *(float2*)&Cf[(size_t)r * DMODEL + gc] = v0;
                *(float2*)&Cf[(size_t)(r + 8) * DMODEL + gc] = v1;
            } else {
                // RoPE: (gc, gc+1) is an (even, odd) pair of head dim i
                int i = (gc & (DK - 1)) >> 1;
                float inv_freq = powf(10000.0f, -((float)(2 * i)) / 128.0f);
                float c0r, s0r, c1r, s1r;
                sincosf((float)s_pos0 * inv_freq, &s0r, &c0r);
                sincosf((float)(s_pos0 + 8) * inv_freq, &s1r, &c1r);
                float re0 = (e0 * c0r - o0 * s0r) * ropescale;
                float ro0 = (e0 * s0r + o0 * c0r) * ropescale;
                float re1 = (e1 * c1r - o1 * s1r) * ropescale;
                float ro1 = (e1 * s1r + o1 * c1r) * ropescale;
                uint32_t h0p, l0p, h1p, l1p;
                splitpack(re0, ro0, h0p, l0p);
                splitpack(re1, ro1, h1p, l1p);
                *(uint32_t*)&Chi[(size_t)r * DMODEL + gc] = h0p;
                *(uint32_t*)&Clo[(size_t)r * DMODEL + gc] = l0p;
                *(uint32_t*)&Chi[(size_t)(r + 8) * DMODEL + gc] = h1p;
                *(uint32_t*)&Clo[(size_t)(r + 8) * DMODEL + gc] = l1p;
            }
        }
    }
}

// ---------------- Flash attention on mma.sync (plane output) -----------------
#define FQH 0
#define FQL 8704
#define FKH 17408
#define FKL 26112
#define FVH 34816
#define FVL 44032
#define FTOT 53248

__global__ __launch_bounds__(128, 2)
void flash_mma(const __nv_bfloat16* __restrict__ Qh, const __nv_bfloat16* __restrict__ Ql,
               const __nv_bfloat16* __restrict__ Kh, const __nv_bfloat16* __restrict__ Kl,
               const __nv_bfloat16* __restrict__ Vh, const __nv_bfloat16* __restrict__ Vl,
               __nv_bfloat16* __restrict__ Ohi, __nv_bfloat16* __restrict__ Olo)
{
    extern __shared__ __nv_bfloat16 sm[];
    const uint32_t sb = smem_u32(sm);
    const int tid = threadIdx.x, lane = tid & 31, warp = tid >> 5;
    const int qblk = blockIdx.x, bh = blockIdx.y;
    const int b = bh >> 4, h = bh & 15, q0 = qblk * 64;
    const int hofs = h * DK;
    const size_t qrow0 = (size_t)(b * SEQ + q0);
    const __nv_bfloat16* vtbase_h = Vh + (size_t)bh * DK * SEQ;
    const __nv_bfloat16* vtbase_l = Vl + (size_t)bh * DK * SEQ;

#pragma unroll
    for (int i = 0; i < 8; i++) {
        int idx = tid + i * 128;
        int r = idx >> 4, c = (idx & 15) * 8;
        cpasync16(sb + (FQH + r * 136 + c) * 2, Qh + (qrow0 + r) * DMODEL + hofs + c);
        cpasync16(sb + (FQL + r * 136 + c) * 2, Ql + (qrow0 + r) * DMODEL + hofs + c);
    }
    CP_COMMIT;

    float o[16][4];
#pragma unroll
    for (int t = 0; t < 16; t++)
#pragma unroll
        for (int e = 0; e < 4; e++) o[t][e] = 0.f;
    float m0v = -INFINITY, m1v = -INFINITY, l0v = 0.f, l1v = 0.f;

    for (int jb = 0; jb <= qblk; ++jb) {
        const int k0 = jb * 64;
        const size_t krow0 = (size_t)(b * SEQ + k0);
#pragma unroll
        for (int i = 0; i < 8; i++) {
            int idx = tid + i * 128;
            int r = idx >> 4, c = (idx & 15) * 8;
            cpasync16(sb + (FKH + r * 136 + c) * 2, Kh + (krow0 + r) * DMODEL + hofs + c);
            cpasync16(sb + (FKL + r * 136 + c) * 2, Kl + (krow0 + r) * DMODEL + hofs + c);
        }
#pragma unroll
        for (int i = 0; i < 8; i++) {
            int idx = tid + i * 128;
            int d = idx >> 3, c = (idx & 7) * 8;
            cpasync16(sb + (FVH + d * 72 + c) * 2, vtbase_h + (size_t)d * SEQ + k0 + c);
            cpasync16(sb + (FVL + d * 72 + c) * 2, vtbase_l + (size_t)d * SEQ + k0 + c);
        }
        CP_COMMIT; cp_wait<0>();
        __syncthreads();

        float s[8][4];
#pragma unroll
        for (int t = 0; t < 8; t++)
#pragma unroll
            for (int e = 0; e < 4; e++) s[t][e] = 0.f;

#pragma unroll
        for (int kc = 0; kc < 8; kc++) {
            int ar = warp * 16 + (lane & 15);
            int ac = kc * 16 + ((lane >> 4) << 3);
            uint32_t aoff = (uint32_t)(ar * 136 + ac) * 2;
            uint32_t qh0, qh1, qh2, qh3, ql0, ql1, ql2, ql3;
            ldmx4(qh0, qh1, qh2, qh3, sb + FQH * 2 + aoff);
            ldmx4(ql0, ql1, ql2, ql3, sb + FQL * 2 + aoff);
#pragma unroll
            for (int np = 0; np < 4; np++) {
                int br = np * 16 + ((lane >> 4) << 3) + (lane & 7);
                int bc = kc * 16 + (((lane >> 3) & 1) << 3);
                uint32_t boff = (uint32_t)(br * 136 + bc) * 2;
                uint32_t kh0, kh1, kh2, kh3, kl0, kl1, kl2, kl3;
                ldmx4(kh0, kh1, kh2, kh3, sb + FKH * 2 + boff);
                ldmx4(kl0, kl1, kl2, kl3, sb + FKL * 2 + boff);
                mma_bf(s[2 * np],     qh0, qh1, qh2, qh3, kh0, kh1);
                mma_bf(s[2 * np],     ql0, ql1, ql2, ql3, kh0, kh1);
                mma_bf(s[2 * np],     qh0, qh1, qh2, qh3, kl0, kl1);
                mma_bf(s[2 * np + 1], qh0, qh1, qh2, qh3, kh2, kh3);
                mma_bf(s[2 * np + 1], ql0, ql1, ql2, ql3, kh2, kh3);
                mma_bf(s[2 * np + 1], qh0, qh1, qh2, qh3, kl2, kl3);
            }
        }

        if (jb == qblk) {
            int r0 = q0 + warp * 16 + (lane >> 2);
#pragma unroll
            for (int t = 0; t < 8; t++) {
                int c0 = k0 + t * 8 + 2 * (lane & 3);
                if (c0 > r0)     s[t][0] = -INFINITY;
                if (c0 + 1 > r0) s[t][1] = -INFINITY;
                if (c0 > r0 + 8)     s[t][2] = -INFINITY;
                if (c0 + 1 > r0 + 8) s[t][3] = -INFINITY;
            }
        }

        float mx0 = -INFINITY, mx1 = -INFINITY;
#pragma unroll
        for (int t = 0; t < 8; t++) {
            mx0 = fmaxf(mx0, fmaxf(s[t][0], s[t][1]));
            mx1 = fmaxf(mx1, fmaxf(s[t][2], s[t][3]));
        }
        mx0 = fmaxf(mx0, __shfl_xor_sync(0xffffffffu, mx0, 1));
        mx0 = fmaxf(mx0, __shfl_xor_sync(0xffffffffu, mx0, 2));
        mx1 = fmaxf(mx1, __shfl_xor_sync(0xffffffffu, mx1, 1));
        mx1 = fmaxf(mx1, __shfl_xor_sync(0xffffffffu, mx1, 2));
        float mn0 = fmaxf(m0v, mx0), mn1 = fmaxf(m1v, mx1);
        float sc0 = __expf(m0v - mn0), sc1 = __expf(m1v - mn1);
        float sum0 = 0.f, sum1 = 0.f;
#pragma unroll
        for (int t = 0; t < 8; t++) {
            s[t][0] = __expf(s[t][0] - mn0); sum0 += s[t][0];
            s[t][1] = __expf(s[t][1] - mn0); sum0 += s[t][1];
            s[t][2] = __expf(s[t][2] - mn1); sum1 += s[t][2];
            s[t][3] = __expf(s[t][3] - mn1); sum1 += s[t][3];
        }
        sum0 += __shfl_xor_sync(0xffffffffu, sum0, 1);
        sum0 += __shfl_xor_sync(0xffffffffu, sum0, 2);
        sum1 += __shfl_xor_sync(0xffffffffu, sum1, 1);
        sum1 += __shfl_xor_sync(0xffffffffu, sum1, 2);
        l0v = l0v * sc0 + sum0; m0v = mn0;
        l1v = l1v * sc1 + sum1; m1v = mn1;

#pragma unroll
        for (int t = 0; t < 16; t++) {
            o[t][0] *= sc0; o[t][1] *= sc0; o[t][2] *= sc1; o[t][3] *= sc1;
        }

#pragma unroll
        for (int kc = 0; kc < 4; kc++) {
            uint32_t ah0, ah1, ah2, ah3, al0, al1, al2, al3;
            splitpack(s[2 * kc][0],     s[2 * kc][1],     ah0, al0);
            splitpack(s[2 * kc][2],     s[2 * kc][3],     ah1, al1);
            splitpack(s[2 * kc + 1][0], s[2 * kc + 1][1], ah2, al2);
            splitpack(s[2 * kc + 1][2], s[2 * kc + 1][3], ah3, al3);
#pragma unroll
            for (int np = 0; np < 8; np++) {
                int br = np * 16 + ((lane >> 4) << 3) + (lane & 7);
                int bc = kc * 16 + (((lane >> 3) & 1) << 3);
                uint32_t boff = (uint32_t)(br * 72 + bc) * 2;
                uint32_t vh0, vh1, vh2, vh3, vl0, vl1, vl2, vl3;
                ldmx4(vh0, vh1, vh2, vh3, sb + FVH * 2 + boff);
                ldmx4(vl0, vl1, vl2, vl3, sb + FVL * 2 + boff);
                mma_bf(o[2 * np],     ah0, ah1, ah2, ah3, vh0, vh1);
                mma_bf(o[2 * np],     al0, al1, al2, al3, vh0, vh1);
                mma_bf(o[2 * np],     ah0, ah1, ah2, ah3, vl0, vl1);
                mma_bf(o[2 * np + 1], ah0, ah1, ah2, ah3, vh2, vh3);
                mma_bf(o[2 * np + 1], al0, al1, al2, al3, vh2, vh3);
                mma_bf(o[2 * np + 1], ah0, ah1, ah2, ah3, vl2, vl3);
            }
        }
        __syncthreads();
    }

    float inv0 = 1.f / l0v, inv1 = 1.f / l1v;
    int r0 = b * SEQ + q0 + warp * 16 + (lane >> 2);
#pragma unroll
    for (int t = 0; t < 16; t++) {
        int gc = hofs + t * 8 + 2 * (lane & 3);
        uint32_t h0p, l0p, h1p, l1p;
        splitpack(o[t][0] * inv0, o[t][1] * inv0, h0p, l0p);
        splitpack(o[t][2] * inv1, o[t][3] * inv1, h1p, l1p);
        *(uint32_t*)&Ohi[(size_t)r0 * DMODEL + gc] = h0p;
        *(uint32_t*)&Olo[(size_t)r0 * DMODEL + gc] = l0p;
        *(uint32_t*)&Ohi[(size_t)(r0 + 8) * DMODEL + gc] = h1p;
        *(uint32_t*)&Olo[(size_t)(r0 + 8) * DMODEL + gc] = l1p;
    }
}

// ---------------- launch ------------------------------------------------------
extern "C" void kernel_launch(void* const* d_in, const int* in_sizes, int n_in,
                              void* d_out, int out_size)
{
    const float* x    = (const float*)d_in[0];
    const float* w[4] = {(const float*)d_in[1], (const float*)d_in[3],
                         (const float*)d_in[5], (const float*)d_in[7]};
    const float* bi[4] = {(const float*)d_in[2], (const float*)d_in[4],
                          (const float*)d_in[6], (const float*)d_in[8]};
    float* out = (float*)d_out;

    float* vb;
    cudaGetSymbolAddress((void**)&vb, g_V);
    __nv_bfloat16 *xh, *xl, *wh, *wl, *ah, *al, *qh, *ql, *kh, *kl, *vth, *vtl;
    cudaGetSymbolAddress((void**)&xh, g_xhi);  cudaGetSymbolAddress((void**)&xl, g_xlo);
    cudaGetSymbolAddress((void**)&wh, g_whi);  cudaGetSymbolAddress((void**)&wl, g_wlo);
    cudaGetSymbolAddress((void**)&ah, g_ahi);  cudaGetSymbolAddress((void**)&al, g_alo);
    cudaGetSymbolAddress((void**)&qh, g_qhi);  cudaGetSymbolAddress((void**)&ql, g_qlo);
    cudaGetSymbolAddress((void**)&kh, g_khi);  cudaGetSymbolAddress((void**)&kl, g_klo);
    cudaGetSymbolAddress((void**)&vth, g_vthi); cudaGetSymbolAddress((void**)&vtl, g_vtlo);

    const size_t WN = (size_t)DMODEL * DMODEL;
    const int ECNT = ROWS * DMODEL / 1024;
    convert_split<<<ECNT, 256>>>(x, xh, xl);
    for (int i = 0; i < 4; i++)
        convert_split<<<WN / 1024, 256>>>(w[i], wh + i * WN, wl + i * WN);

    size_t gsmem = 2 * STGE * sizeof(__nv_bfloat16);
    cudaFuncSetAttribute(gemm_bf16x3<0>, cudaFuncAttributeMaxDynamicSharedMemorySize,
                         (int)gsmem);
    cudaFuncSetAttribute(gemm_bf16x3<1>, cudaFuncAttributeMaxDynamicSharedMemorySize,
                         (int)gsmem);
    dim3 ggrid(DMODEL / 128, ROWS / 128);
    gemm_bf16x3<1><<<ggrid, 256, gsmem>>>(xh, xl, wh + 0 * WN, wl + 0 * WN, bi[0],
                                          nullptr, qh, ql, 0.08838834764831843f);
    gemm_bf16x3<1><<<ggrid, 256, gsmem>>>(xh, xl, wh + 1 * WN, wl + 1 * WN, bi[1],
                                          nullptr, kh, kl, 1.0f);
    gemm_bf16x3<0><<<ggrid, 256, gsmem>>>(xh, xl, wh + 2 * WN, wl + 2 * WN, bi[2],
                                          vb, nullptr, nullptr, 0.f);

    dim3 vgrid(SEQ / 32, DK / 32, BATCH * NHEADS);
    convert_vt<<<vgrid, 256>>>(vb, vth, vtl);

    size_t fsmem = FTOT * sizeof(__nv_bfloat16);
    cudaFuncSetAttribute(flash_mma, cudaFuncAttributeMaxDynamicSharedMemorySize,
                         (int)fsmem);
    dim3 fgrid(SEQ / 64, BATCH * NHEADS);
    flash_mma<<<fgrid, 128, fsmem>>>(qh, ql, kh, kl, vth, vtl, ah, al);

    gemm_bf16x3<0><<<ggrid, 256, gsmem>>>(ah, al, wh + 3 * WN, wl + 3 * WN, bi[3],
                                          out, nullptr, nullptr, 0.f);
}

// round 8
// speedup vs baseline: 3.2282x; 1.2096x over previous
#include <cuda_runtime.h>
#include <cuda_bf16.h>
#include <cuda_fp16.h>
#include <math.h>
#include <stdint.h>

#define BATCH   2
#define SEQ     2048
#define DMODEL  2048
#define NHEADS  16
#define DK      128
#define ROWS    (BATCH * SEQ)
#define WN      (DMODEL * DMODEL)

// ---------------- scratch ----------------------------------------------------
__device__ float g_V[ROWS * DMODEL];
__device__ __nv_bfloat16 g_xhi[ROWS * DMODEL],  g_xlo[ROWS * DMODEL];
__device__ __nv_bfloat16 g_whi[3][WN], g_wlo[3][WN];
__device__ __half        g_wo16[WN];
__device__ __half        g_a16[ROWS * DMODEL];
__device__ __nv_bfloat16 g_qhi[ROWS * DMODEL],  g_qlo[ROWS * DMODEL];
__device__ __nv_bfloat16 g_khi[ROWS * DMODEL],  g_klo[ROWS * DMODEL];
__device__ __nv_bfloat16 g_vthi[ROWS * DMODEL], g_vtlo[ROWS * DMODEL];

// ---------------- helpers ----------------------------------------------------
__device__ __forceinline__ uint32_t smem_u32(const void* p) {
    return (uint32_t)__cvta_generic_to_shared(p);
}
__device__ __forceinline__ void ldmx4(uint32_t& r0, uint32_t& r1, uint32_t& r2,
                                      uint32_t& r3, uint32_t a) {
    asm volatile("ldmatrix.sync.aligned.m8n8.x4.shared.b16 {%0,%1,%2,%3},[%4];"
                 : "=r"(r0), "=r"(r1), "=r"(r2), "=r"(r3) : "r"(a));
}
__device__ __forceinline__ void mma_bf(float* c, uint32_t a0, uint32_t a1,
                                       uint32_t a2, uint32_t a3,
                                       uint32_t b0, uint32_t b1) {
    asm volatile(
        "mma.sync.aligned.m16n8k16.row.col.f32.bf16.bf16.f32 "
        "{%0,%1,%2,%3},{%4,%5,%6,%7},{%8,%9},{%0,%1,%2,%3};"
        : "+f"(c[0]), "+f"(c[1]), "+f"(c[2]), "+f"(c[3])
        : "r"(a0), "r"(a1), "r"(a2), "r"(a3), "r"(b0), "r"(b1));
}
__device__ __forceinline__ void mma_f16(float* c, uint32_t a0, uint32_t a1,
                                        uint32_t a2, uint32_t a3,
                                        uint32_t b0, uint32_t b1) {
    asm volatile(
        "mma.sync.aligned.m16n8k16.row.col.f32.f16.f16.f32 "
        "{%0,%1,%2,%3},{%4,%5,%6,%7},{%8,%9},{%0,%1,%2,%3};"
        : "+f"(c[0]), "+f"(c[1]), "+f"(c[2]), "+f"(c[3])
        : "r"(a0), "r"(a1), "r"(a2), "r"(a3), "r"(b0), "r"(b1));
}
__device__ __forceinline__ void cpasync16(uint32_t dst, const void* src) {
    asm volatile("cp.async.cg.shared.global [%0],[%1],16;" :: "r"(dst), "l"(src));
}
#define CP_COMMIT asm volatile("cp.async.commit_group;")
template<int N> __device__ __forceinline__ void cp_wait() {
    asm volatile("cp.async.wait_group %0;" :: "n"(N));
}
__device__ __forceinline__ void split2(float v, __nv_bfloat16& h, __nv_bfloat16& l) {
    h = __float2bfloat16(v);
    l = __float2bfloat16(v - __bfloat162float(h));
}
__device__ __forceinline__ void splitpack(float x, float y, uint32_t& h, uint32_t& l) {
    __nv_bfloat162 hh, ll;
    split2(x, hh.x, ll.x); split2(y, hh.y, ll.y);
    h = *(uint32_t*)&hh; l = *(uint32_t*)&ll;
}

// ---------------- converts ---------------------------------------------------
__global__ __launch_bounds__(256)
void convert_x(const float* __restrict__ in, __nv_bfloat16* __restrict__ hi,
               __nv_bfloat16* __restrict__ lo)
{
    int i = (blockIdx.x * blockDim.x + threadIdx.x) * 4;
    float4 v = *(const float4*)(in + i);
    __nv_bfloat162 h0, h1, l0, l1;
    split2(v.x, h0.x, l0.x); split2(v.y, h0.y, l0.y);
    split2(v.z, h1.x, l1.x); split2(v.w, h1.y, l1.y);
    *(__nv_bfloat162*)&hi[i]     = h0;  *(__nv_bfloat162*)&hi[i + 2] = h1;
    *(__nv_bfloat162*)&lo[i]     = l0;  *(__nv_bfloat162*)&lo[i + 2] = l1;
}

__global__ __launch_bounds__(256)
void convert_w(const float* __restrict__ w0, const float* __restrict__ w1,
               const float* __restrict__ w2, const float* __restrict__ w3,
               __nv_bfloat16* __restrict__ whi, __nv_bfloat16* __restrict__ wlo,
               __half* __restrict__ wo16)
{
    int z = blockIdx.y;
    const float* src = (z == 0) ? w0 : (z == 1) ? w1 : (z == 2) ? w2 : w3;
    int i = (blockIdx.x * blockDim.x + threadIdx.x) * 4;
    float4 v = *(const float4*)(src + i);
    if (z < 3) {
        __nv_bfloat162 h0, h1, l0, l1;
        split2(v.x, h0.x, l0.x); split2(v.y, h0.y, l0.y);
        split2(v.z, h1.x, l1.x); split2(v.w, h1.y, l1.y);
        __nv_bfloat16* hi = whi + (size_t)z * WN;
        __nv_bfloat16* lo = wlo + (size_t)z * WN;
        *(__nv_bfloat162*)&hi[i]     = h0;  *(__nv_bfloat162*)&hi[i + 2] = h1;
        *(__nv_bfloat162*)&lo[i]     = l0;  *(__nv_bfloat162*)&lo[i + 2] = l1;
    } else {
        __half2 a = __floats2half2_rn(v.x, v.y);
        __half2 b = __floats2half2_rn(v.z, v.w);
        *(uint32_t*)&wo16[i]     = *(uint32_t*)&a;
        *(uint32_t*)&wo16[i + 2] = *(uint32_t*)&b;
    }
}

__global__ __launch_bounds__(256)
void convert_vt(const float* __restrict__ V, __nv_bfloat16* __restrict__ hi,
                __nv_bfloat16* __restrict__ lo)
{
    __shared__ float t[32][33];
    int bh = blockIdx.z, b = bh >> 4, h = bh & 15;
    int s0 = blockIdx.x * 32, d0 = blockIdx.y * 32;
    int lx = threadIdx.x & 31, ly = threadIdx.x >> 5;
#pragma unroll
    for (int i = 0; i < 4; i++) {
        int sl = ly + i * 8;
        t[sl][lx] = V[(size_t)(b * SEQ + s0 + sl) * DMODEL + h * DK + d0 + lx];
    }
    __syncthreads();
#pragma unroll
    for (int i = 0; i < 4; i++) {
        int dl = ly + i * 8;
        __nv_bfloat16 hh, ll; split2(t[lx][dl], hh, ll);
        size_t o = (size_t)(bh * DK + d0 + dl) * SEQ + s0 + lx;
        hi[o] = hh; lo[o] = ll;
    }
}

// ---------------- merged QKV GEMM (bf16x3, grid.z selects output) ------------
#define NKIT (DMODEL / 32)
#define PLE  (128 * 40)
#define STGE (4 * PLE)

__global__ __launch_bounds__(256, 2)
void gemm_qkv(const __nv_bfloat16* __restrict__ Ahi, const __nv_bfloat16* __restrict__ Alo,
              const __nv_bfloat16* __restrict__ Whi, const __nv_bfloat16* __restrict__ Wlo,
              const float* __restrict__ b0, const float* __restrict__ b1,
              const float* __restrict__ b2,
              __nv_bfloat16* __restrict__ qh, __nv_bfloat16* __restrict__ ql,
              __nv_bfloat16* __restrict__ kh, __nv_bfloat16* __restrict__ kl,
              float* __restrict__ Vf)
{
    extern __shared__ __nv_bfloat16 sm[];
    const int tid = threadIdx.x, lane = tid & 31, wid = tid >> 5;
    const int wm = wid & 3, wn = wid >> 2;
    const int m0 = blockIdx.y * 128, n0 = blockIdx.x * 128;
    const int bz = blockIdx.z;
    const uint32_t sb = smem_u32(sm);
    const __nv_bfloat16* srcs[4] = {Ahi, Alo,
                                    Whi + (size_t)bz * WN, Wlo + (size_t)bz * WN};
    const float* bias = (bz == 0) ? b0 : (bz == 1) ? b1 : b2;

    auto issue = [&](int kt, int stg) {
        int kofs = kt * 32;
#pragma unroll
        for (int i = 0; i < 8; i++) {
            int idx = tid + i * 256;
            int plane = idx >> 9, rem = idx & 511;
            int row = rem >> 2, ch = (rem & 3) * 8;
            int grow = (plane < 2 ? m0 : n0) + row;
            cpasync16(sb + (stg * STGE + plane * PLE + row * 40 + ch) * 2,
                      srcs[plane] + (size_t)grow * DMODEL + kofs + ch);
        }
    };

    float acc[2][8][4];
#pragma unroll
    for (int a = 0; a < 2; a++)
#pragma unroll
        for (int b = 0; b < 8; b++)
#pragma unroll
            for (int c = 0; c < 4; c++) acc[a][b][c] = 0.f;

    issue(0, 0); CP_COMMIT;

    for (int kt = 0; kt < NKIT; kt++) {
        cp_wait<0>();
        __syncthreads();
        if (kt + 1 < NKIT) { issue(kt + 1, (kt + 1) & 1); CP_COMMIT; }
        uint32_t s0 = sb + ((kt & 1) * STGE) * 2;

#pragma unroll
        for (int ks = 0; ks < 32; ks += 16) {
            uint32_t ah[2][4], al[2][4];
#pragma unroll
            for (int mt = 0; mt < 2; mt++) {
                int ar = wm * 32 + mt * 16 + (lane & 15);
                int ac = ks + ((lane >> 4) << 3);
                uint32_t off = (uint32_t)(ar * 40 + ac) * 2;
                ldmx4(ah[mt][0], ah[mt][1], ah[mt][2], ah[mt][3], s0 + off);
                ldmx4(al[mt][0], al[mt][1], al[mt][2], al[mt][3], s0 + PLE * 2 + off);
            }
#pragma unroll
            for (int np = 0; np < 4; np++) {
                int br = wn * 64 + np * 16 + ((lane >> 4) << 3) + (lane & 7);
                int bc = ks + (((lane >> 3) & 1) << 3);
                uint32_t off = (uint32_t)(br * 40 + bc) * 2;
                uint32_t h0, h1, h2, h3, q0, q1, q2, q3;
                ldmx4(h0, h1, h2, h3, s0 + PLE * 4 + off);
                ldmx4(q0, q1, q2, q3, s0 + PLE * 6 + off);
#pragma unroll
                for (int mt = 0; mt < 2; mt++) {
                    float* c0 = acc[mt][2 * np];
                    float* c1 = acc[mt][2 * np + 1];
                    mma_bf(c0, ah[mt][0], ah[mt][1], ah[mt][2], ah[mt][3], h0, h1);
                    mma_bf(c0, ah[mt][0], ah[mt][1], ah[mt][2], ah[mt][3], q0, q1);
                    mma_bf(c0, al[mt][0], al[mt][1], al[mt][2], al[mt][3], h0, h1);
                    mma_bf(c1, ah[mt][0], ah[mt][1], ah[mt][2], ah[mt][3], h2, h3);
                    mma_bf(c1, ah[mt][0], ah[mt][1], ah[mt][2], ah[mt][3], q2, q3);
                    mma_bf(c1, al[mt][0], al[mt][1], al[mt][2], al[mt][3], h2, h3);
                }
            }
        }
        __syncthreads();
    }

    const float ropescale = (bz == 0) ? 0.08838834764831843f : 1.0f;
    __nv_bfloat16* Chi = (bz == 0) ? qh : kh;
    __nv_bfloat16* Clo = (bz == 0) ? ql : kl;

#pragma unroll
    for (int mt = 0; mt < 2; mt++) {
        int r = m0 + wm * 32 + mt * 16 + (lane >> 2);
        int s_pos0 = r & (SEQ - 1);
#pragma unroll
        for (int nt = 0; nt < 8; nt++) {
            int gc = n0 + wn * 64 + nt * 8 + (lane & 3) * 2;
            float bb0 = bias[gc], bb1 = bias[gc + 1];
            float e0 = acc[mt][nt][0] + bb0, o0 = acc[mt][nt][1] + bb1;
            float e1 = acc[mt][nt][2] + bb0, o1 = acc[mt][nt][3] + bb1;
            if (bz == 2) {
                float2 v0 = {e0, o0}, v1 = {e1, o1};
                *(float2*)&Vf[(size_t)r * DMODEL + gc] = v0;
                *(float2*)&Vf[(size_t)(r + 8) * DMODEL + gc] = v1;
            } else {
                int i = (gc & (DK - 1)) >> 1;
                float inv_freq = powf(10000.0f, -((float)(2 * i)) / 128.0f);
                float c0r, s0r, c1r, s1r;
                sincosf((float)s_pos0 * inv_freq, &s0r, &c0r);
                sincosf((float)(s_pos0 + 8) * inv_freq, &s1r, &c1r);
                float re0 = (e0 * c0r - o0 * s0r) * ropescale;
                float ro0 = (e0 * s0r + o0 * c0r) * ropescale;
                float re1 = (e1 * c1r - o1 * s1r) * ropescale;
                float ro1 = (e1 * s1r + o1 * c1r) * ropescale;
                uint32_t h0p, l0p, h1p, l1p;
                splitpack(re0, ro0, h0p, l0p);
                splitpack(re1, ro1, h1p, l1p);
                *(uint32_t*)&Chi[(size_t)r * DMODEL + gc] = h0p;
                *(uint32_t*)&Clo[(size_t)r * DMODEL + gc] = l0p;
                *(uint32_t*)&Chi[(size_t)(r + 8) * DMODEL + gc] = h1p;
                *(uint32_t*)&Clo[(size_t)(r + 8) * DMODEL + gc] = l1p;
            }
        }
    }
}

// ---------------- fp16 single-mma GEMM (output projection) -------------------
#define PLE16  (128 * 40)
#define STGE16 (2 * PLE16)

__global__ __launch_bounds__(256, 2)
void gemm_f16(const __half* __restrict__ A, const __half* __restrict__ B,
              const float* __restrict__ bias, float* __restrict__ C)
{
    extern __shared__ __half smh[];
    const int tid = threadIdx.x, lane = tid & 31, wid = tid >> 5;
    const int wm = wid & 3, wn = wid >> 2;
    const int m0 = blockIdx.y * 128, n0 = blockIdx.x * 128;
    const uint32_t sb = smem_u32(smh);

    auto issue = [&](int kt, int stg) {
        int kofs = kt * 32;
#pragma unroll
        for (int i = 0; i < 4; i++) {
            int idx = tid + i * 256;
            int plane = idx >> 9, rem = idx & 511;
            int row = rem >> 2, ch = (rem & 3) * 8;
            const __half* src = plane ? (B + (size_t)(n0 + row) * DMODEL + kofs + ch)
                                      : (A + (size_t)(m0 + row) * DMODEL + kofs + ch);
            cpasync16(sb + (stg * STGE16 + plane * PLE16 + row * 40 + ch) * 2, src);
        }
    };

    float acc[2][8][4];
#pragma unroll
    for (int a = 0; a < 2; a++)
#pragma unroll
        for (int b = 0; b < 8; b++)
#pragma unroll
            for (int c = 0; c < 4; c++) acc[a][b][c] = 0.f;

    issue(0, 0); CP_COMMIT;

    for (int kt = 0; kt < NKIT; kt++) {
        cp_wait<0>();
        __syncthreads();
        if (kt + 1 < NKIT) { issue(kt + 1, (kt + 1) & 1); CP_COMMIT; }
        uint32_t s0 = sb + ((kt & 1) * STGE16) * 2;

#pragma unroll
        for (int ks = 0; ks < 32; ks += 16) {
            uint32_t av[2][4];
#pragma unroll
            for (int mt = 0; mt < 2; mt++) {
                int ar = wm * 32 + mt * 16 + (lane & 15);
                int ac = ks + ((lane >> 4) << 3);
                uint32_t off = (uint32_t)(ar * 40 + ac) * 2;
                ldmx4(av[mt][0], av[mt][1], av[mt][2], av[mt][3], s0 + off);
            }
#pragma unroll
            for (int np = 0; np < 4; np++) {
                int br = wn * 64 + np * 16 + ((lane >> 4) << 3) + (lane & 7);
                int bc = ks + (((lane >> 3) & 1) << 3);
                uint32_t off = (uint32_t)(br * 40 + bc) * 2;
                uint32_t b0, b1, b2, b3;
                ldmx4(b0, b1, b2, b3, s0 + PLE16 * 2 + off);
#pragma unroll
                for (int mt = 0; mt < 2; mt++) {
                    mma_f16(acc[mt][2 * np],     av[mt][0], av[mt][1], av[mt][2], av[mt][3], b0, b1);
                    mma_f16(acc[mt][2 * np + 1], av[mt][0], av[mt][1], av[mt][2], av[mt][3], b2, b3);
                }
            }
        }
        __syncthreads();
    }

#pragma unroll
    for (int mt = 0; mt < 2; mt++) {
        int r = m0 + wm * 32 + mt * 16 + (lane >> 2);
#pragma unroll
        for (int nt = 0; nt < 8; nt++) {
            int gc = n0 + wn * 64 + nt * 8 + (lane & 3) * 2;
            float bb0 = bias[gc], bb1 = bias[gc + 1];
            float2 v0 = {acc[mt][nt][0] + bb0, acc[mt][nt][1] + bb1};
            float2 v1 = {acc[mt][nt][2] + bb0, acc[mt][nt][3] + bb1};
            *(float2*)&C[(size_t)r * DMODEL + gc] = v0;
            *(float2*)&C[(size_t)(r + 8) * DMODEL + gc] = v1;
        }
    }
}

// ---------------- Flash attention (fp16 plane output) ------------------------
#define FQH 0
#define FQL 8704
#define FKH 17408
#define FKL 26112
#define FVH 34816
#define FVL 44032
#define FTOT 53248

__global__ __launch_bounds__(128, 2)
void flash_mma(const __nv_bfloat16* __restrict__ Qh, const __nv_bfloat16* __restrict__ Ql,
               const __nv_bfloat16* __restrict__ Kh, const __nv_bfloat16* __restrict__ Kl,
               const __nv_bfloat16* __restrict__ Vh, const __nv_bfloat16* __restrict__ Vl,
               __half* __restrict__ A16)
{
    extern __shared__ __nv_bfloat16 sm[];
    const uint32_t sb = smem_u32(sm);
    const int tid = threadIdx.x, lane = tid & 31, warp = tid >> 5;
    const int qblk = blockIdx.x, bh = blockIdx.y;
    const int b = bh >> 4, h = bh & 15, q0 = qblk * 64;
    const int hofs = h * DK;
    const size_t qrow0 = (size_t)(b * SEQ + q0);
    const __nv_bfloat16* vtbase_h = Vh + (size_t)bh * DK * SEQ;
    const __nv_bfloat16* vtbase_l = Vl + (size_t)bh * DK * SEQ;

#pragma unroll
    for (int i = 0; i < 8; i++) {
        int idx = tid + i * 128;
        int r = idx >> 4, c = (idx & 15) * 8;
        cpasync16(sb + (FQH + r * 136 + c) * 2, Qh + (qrow0 + r) * DMODEL + hofs + c);
        cpasync16(sb + (FQL + r * 136 + c) * 2, Ql + (qrow0 + r) * DMODEL + hofs + c);
    }
    CP_COMMIT;

    float o[16][4];
#pragma unroll
    for (int t = 0; t < 16; t++)
#pragma unroll
        for (int e = 0; e < 4; e++) o[t][e] = 0.f;
    float m0v = -INFINITY, m1v = -INFINITY, l0v = 0.f, l1v = 0.f;

    for (int jb = 0; jb <= qblk; ++jb) {
        const int k0 = jb * 64;
        const size_t krow0 = (size_t)(b * SEQ + k0);
#pragma unroll
        for (int i = 0; i < 8; i++) {
            int idx = tid + i * 128;
            int r = idx >> 4, c = (idx & 15) * 8;
            cpasync16(sb + (FKH + r * 136 + c) * 2, Kh + (krow0 + r) * DMODEL + hofs + c);
            cpasync16(sb + (FKL + r * 136 + c) * 2, Kl + (krow0 + r) * DMODEL + hofs + c);
        }
#pragma unroll
        for (int i = 0; i < 8; i++) {
            int idx = tid + i * 128;
            int d = idx >> 3, c = (idx & 7) * 8;
            cpasync16(sb + (FVH + d * 72 + c) * 2, vtbase_h + (size_t)d * SEQ + k0 + c);
            cpasync16(sb + (FVL + d * 72 + c) * 2, vtbase_l + (size_t)d * SEQ + k0 + c);
        }
        CP_COMMIT; cp_wait<0>();
        __syncthreads();

        float s[8][4];
#pragma unroll
        for (int t = 0; t < 8; t++)
#pragma unroll
            for (int e = 0; e < 4; e++) s[t][e] = 0.f;

#pragma unroll
        for (int kc = 0; kc < 8; kc++) {
            int ar = warp * 16 + (lane & 15);
            int ac = kc * 16 + ((lane >> 4) << 3);
            uint32_t aoff = (uint32_t)(ar * 136 + ac) * 2;
            uint32_t qh0, qh1, qh2, qh3, ql0, ql1, ql2, ql3;
            ldmx4(qh0, qh1, qh2, qh3, sb + FQH * 2 + aoff);
            ldmx4(ql0, ql1, ql2, ql3, sb + FQL * 2 + aoff);
#pragma unroll
            for (int np = 0; np < 4; np++) {
                int br = np * 16 + ((lane >> 4) << 3) + (lane & 7);
                int bc = kc * 16 + (((lane >> 3) & 1) << 3);
                uint32_t boff = (uint32_t)(br * 136 + bc) * 2;
                uint32_t kh0, kh1, kh2, kh3, kl0, kl1, kl2, kl3;
                ldmx4(kh0, kh1, kh2, kh3, sb + FKH * 2 + boff);
                ldmx4(kl0, kl1, kl2, kl3, sb + FKL * 2 + boff);
                mma_bf(s[2 * np],     qh0, qh1, qh2, qh3, kh0, kh1);
                mma_bf(s[2 * np],     ql0, ql1, ql2, ql3, kh0, kh1);
                mma_bf(s[2 * np],     qh0, qh1, qh2, qh3, kl0, kl1);
                mma_bf(s[2 * np + 1], qh0, qh1, qh2, qh3, kh2, kh3);
                mma_bf(s[2 * np + 1], ql0, ql1, ql2, ql3, kh2, kh3);
                mma_bf(s[2 * np + 1], qh0, qh1, qh2, qh3, kl2, kl3);
            }
        }

        if (jb == qblk) {
            int r0 = q0 + warp * 16 + (lane >> 2);
#pragma unroll
            for (int t = 0; t < 8; t++) {
                int c0 = k0 + t * 8 + 2 * (lane & 3);
                if (c0 > r0)     s[t][0] = -INFINITY;
                if (c0 + 1 > r0) s[t][1] = -INFINITY;
                if (c0 > r0 + 8)     s[t][2] = -INFINITY;
                if (c0 + 1 > r0 + 8) s[t][3] = -INFINITY;
            }
        }

        float mx0 = -INFINITY, mx1 = -INFINITY;
#pragma unroll
        for (int t = 0; t < 8; t++) {
            mx0 = fmaxf(mx0, fmaxf(s[t][0], s[t][1]));
            mx1 = fmaxf(mx1, fmaxf(s[t][2], s[t][3]));
        }
        mx0 = fmaxf(mx0, __shfl_xor_sync(0xffffffffu, mx0, 1));
        mx0 = fmaxf(mx0, __shfl_xor_sync(0xffffffffu, mx0, 2));
        mx1 = fmaxf(mx1, __shfl_xor_sync(0xffffffffu, mx1, 1));
        mx1 = fmaxf(mx1, __shfl_xor_sync(0xffffffffu, mx1, 2));
        float mn0 = fmaxf(m0v, mx0), mn1 = fmaxf(m1v, mx1);
        float sc0 = __expf(m0v - mn0), sc1 = __expf(m1v - mn1);
        float sum0 = 0.f, sum1 = 0.f;
#pragma unroll
        for (int t = 0; t < 8; t++) {
            s[t][0] = __expf(s[t][0] - mn0); sum0 += s[t][0];
            s[t][1] = __expf(s[t][1] - mn0); sum0 += s[t][1];
            s[t][2] = __expf(s[t][2] - mn1); sum1 += s[t][2];
            s[t][3] = __expf(s[t][3] - mn1); sum1 += s[t][3];
        }
        sum0 += __shfl_xor_sync(0xffffffffu, sum0, 1);
        sum0 += __shfl_xor_sync(0xffffffffu, sum0, 2);
        sum1 += __shfl_xor_sync(0xffffffffu, sum1, 1);
        sum1 += __shfl_xor_sync(0xffffffffu, sum1, 2);
        l0v = l0v * sc0 + sum0; m0v = mn0;
        l1v = l1v * sc1 + sum1; m1v = mn1;

#pragma unroll
        for (int t = 0; t < 16; t++) {
            o[t][0] *= sc0; o[t][1] *= sc0; o[t][2] *= sc1; o[t][3] *= sc1;
        }

#pragma unroll
        for (int kc = 0; kc < 4; kc++) {
            uint32_t ah0, ah1, ah2, ah3, al0, al1, al2, al3;
            splitpack(s[2 * kc][0],     s[2 * kc][1],     ah0, al0);
            splitpack(s[2 * kc][2],     s[2 * kc][3],     ah1, al1);
            splitpack(s[2 * kc + 1][0], s[2 * kc + 1][1], ah2, al2);
            splitpack(s[2 * kc + 1][2], s[2 * kc + 1][3], ah3, al3);
#pragma unroll
            for (int np = 0; np < 8; np++) {
                int br = np * 16 + ((lane >> 4) << 3) + (lane & 7);
                int bc = kc * 16 + (((lane >> 3) & 1) << 3);
                uint32_t boff = (uint32_t)(br * 72 + bc) * 2;
                uint32_t vh0, vh1, vh2, vh3, vl0, vl1, vl2, vl3;
                ldmx4(vh0, vh1, vh2, vh3, sb + FVH * 2 + boff);
                ldmx4(vl0, vl1, vl2, vl3, sb + FVL * 2 + boff);
                mma_bf(o[2 * np],     ah0, ah1, ah2, ah3, vh0, vh1);
                mma_bf(o[2 * np],     al0, al1, al2, al3, vh0, vh1);
                mma_bf(o[2 * np],     ah0, ah1, ah2, ah3, vl0, vl1);
                mma_bf(o[2 * np + 1], ah0, ah1, ah2, ah3, vh2, vh3);
                mma_bf(o[2 * np + 1], al0, al1, al2, al3, vh2, vh3);
                mma_bf(o[2 * np + 1], ah0, ah1, ah2, ah3, vl2, vl3);
            }
        }
        __syncthreads();
    }

    float inv0 = 1.f / l0v, inv1 = 1.f / l1v;
    int r0 = b * SEQ + q0 + warp * 16 + (lane >> 2);
#pragma unroll
    for (int t = 0; t < 16; t++) {
        int gc = hofs + t * 8 + 2 * (lane & 3);
        __half2 h0 = __floats2half2_rn(o[t][0] * inv0, o[t][1] * inv0);
        __half2 h1 = __floats2half2_rn(o[t][2] * inv1, o[t][3] * inv1);
        *(uint32_t*)&A16[(size_t)r0 * DMODEL + gc] = *(uint32_t*)&h0;
        *(uint32_t*)&A16[(size_t)(r0 + 8) * DMODEL + gc] = *(uint32_t*)&h1;
    }
}

// ---------------- launch ------------------------------------------------------
extern "C" void kernel_launch(void* const* d_in, const int* in_sizes, int n_in,
                              void* d_out, int out_size)
{
    const float* x    = (const float*)d_in[0];
    const float* w[4] = {(const float*)d_in[1], (const float*)d_in[3],
                         (const float*)d_in[5], (const float*)d_in[7]};
    const float* bi[4] = {(const float*)d_in[2], (const float*)d_in[4],
                          (const float*)d_in[6], (const float*)d_in[8]};
    float* out = (float*)d_out;

    float* vb;
    cudaGetSymbolAddress((void**)&vb, g_V);
    __nv_bfloat16 *xh, *xl, *wh, *wl, *qh, *ql, *kh, *kl, *vth, *vtl;
    __half *wo16, *a16;
    cudaGetSymbolAddress((void**)&xh, g_xhi);  cudaGetSymbolAddress((void**)&xl, g_xlo);
    cudaGetSymbolAddress((void**)&wh, g_whi);  cudaGetSymbolAddress((void**)&wl, g_wlo);
    cudaGetSymbolAddress((void**)&qh, g_qhi);  cudaGetSymbolAddress((void**)&ql, g_qlo);
    cudaGetSymbolAddress((void**)&kh, g_khi);  cudaGetSymbolAddress((void**)&kl, g_klo);
    cudaGetSymbolAddress((void**)&vth, g_vthi); cudaGetSymbolAddress((void**)&vtl, g_vtlo);
    cudaGetSymbolAddress((void**)&wo16, g_wo16);
    cudaGetSymbolAddress((void**)&a16, g_a16);

    convert_x<<<ROWS * DMODEL / 1024, 256>>>(x, xh, xl);
    convert_w<<<dim3(WN / 1024, 4), 256>>>(w[0], w[1], w[2], w[3], wh, wl, wo16);

    size_t gsmem = 2 * STGE * sizeof(__nv_bfloat16);
    cudaFuncSetAttribute(gemm_qkv, cudaFuncAttributeMaxDynamicSharedMemorySize,
                         (int)gsmem);
    gemm_qkv<<<dim3(DMODEL / 128, ROWS / 128, 3), 256, gsmem>>>(
        xh, xl, wh, wl, bi[0], bi[1], bi[2], qh, ql, kh, kl, vb);

    convert_vt<<<dim3(SEQ / 32, DK / 32, BATCH * NHEADS), 256>>>(vb, vth, vtl);

    size_t fsmem = FTOT * sizeof(__nv_bfloat16);
    cudaFuncSetAttribute(flash_mma, cudaFuncAttributeMaxDynamicSharedMemorySize,
                         (int)fsmem);
    flash_mma<<<dim3(SEQ / 64, BATCH * NHEADS), 128, fsmem>>>(
        qh, ql, kh, kl, vth, vtl, a16);

    size_t g16smem = 2 * STGE16 * sizeof(__half);
    cudaFuncSetAttribute(gemm_f16, cudaFuncAttributeMaxDynamicSharedMemorySize,
                         (int)g16smem);
    gemm_f16<<<dim3(DMODEL / 128, ROWS / 128), 256, g16smem>>>(a16, wo16, bi[3], out);
}

// round 9
// speedup vs baseline: 4.0190x; 1.2449x over previous
#include <cuda_runtime.h>
#include <cuda_bf16.h>
#include <cuda_fp16.h>
#include <math.h>
#include <stdint.h>

#define BATCH   2
#define SEQ     2048
#define DMODEL  2048
#define NHEADS  16
#define DK      128
#define ROWS    (BATCH * SEQ)
#define WN      (DMODEL * DMODEL)

// ---------------- scratch ----------------------------------------------------
__device__ float g_V[ROWS * DMODEL];
__device__ __nv_bfloat16 g_xhi[ROWS * DMODEL],  g_xlo[ROWS * DMODEL];
__device__ __half        g_x16[ROWS * DMODEL];
__device__ __nv_bfloat16 g_whi[2][WN], g_wlo[2][WN];
__device__ __half        g_wv16[WN], g_wo16[WN];
__device__ __half        g_a16[ROWS * DMODEL];
__device__ __nv_bfloat16 g_qhi[ROWS * DMODEL],  g_qlo[ROWS * DMODEL];
__device__ __nv_bfloat16 g_khi[ROWS * DMODEL],  g_klo[ROWS * DMODEL];
__device__ __half        g_vt16[ROWS * DMODEL];   // [bh][d][s]

// ---------------- helpers ----------------------------------------------------
__device__ __forceinline__ uint32_t smem_u32(const void* p) {
    return (uint32_t)__cvta_generic_to_shared(p);
}
__device__ __forceinline__ void ldmx4(uint32_t& r0, uint32_t& r1, uint32_t& r2,
                                      uint32_t& r3, uint32_t a) {
    asm volatile("ldmatrix.sync.aligned.m8n8.x4.shared.b16 {%0,%1,%2,%3},[%4];"
                 : "=r"(r0), "=r"(r1), "=r"(r2), "=r"(r3) : "r"(a));
}
__device__ __forceinline__ void mma_bf(float* c, uint32_t a0, uint32_t a1,
                                       uint32_t a2, uint32_t a3,
                                       uint32_t b0, uint32_t b1) {
    asm volatile(
        "mma.sync.aligned.m16n8k16.row.col.f32.bf16.bf16.f32 "
        "{%0,%1,%2,%3},{%4,%5,%6,%7},{%8,%9},{%0,%1,%2,%3};"
        : "+f"(c[0]), "+f"(c[1]), "+f"(c[2]), "+f"(c[3])
        : "r"(a0), "r"(a1), "r"(a2), "r"(a3), "r"(b0), "r"(b1));
}
__device__ __forceinline__ void mma_f16(float* c, uint32_t a0, uint32_t a1,
                                        uint32_t a2, uint32_t a3,
                                        uint32_t b0, uint32_t b1) {
    asm volatile(
        "mma.sync.aligned.m16n8k16.row.col.f32.f16.f16.f32 "
        "{%0,%1,%2,%3},{%4,%5,%6,%7},{%8,%9},{%0,%1,%2,%3};"
        : "+f"(c[0]), "+f"(c[1]), "+f"(c[2]), "+f"(c[3])
        : "r"(a0), "r"(a1), "r"(a2), "r"(a3), "r"(b0), "r"(b1));
}
__device__ __forceinline__ void cpasync16(uint32_t dst, const void* src) {
    asm volatile("cp.async.cg.shared.global [%0],[%1],16;" :: "r"(dst), "l"(src));
}
#define CP_COMMIT asm volatile("cp.async.commit_group;")
template<int N> __device__ __forceinline__ void cp_wait() {
    asm volatile("cp.async.wait_group %0;" :: "n"(N));
}
__device__ __forceinline__ void split2(float v, __nv_bfloat16& h, __nv_bfloat16& l) {
    h = __float2bfloat16(v);
    l = __float2bfloat16(v - __bfloat162float(h));
}
__device__ __forceinline__ void splitpack(float x, float y, uint32_t& h, uint32_t& l) {
    __nv_bfloat162 hh, ll;
    split2(x, hh.x, ll.x); split2(y, hh.y, ll.y);
    h = *(uint32_t*)&hh; l = *(uint32_t*)&ll;
}
__device__ __forceinline__ uint32_t packh2(float x, float y) {
    __half2 h = __floats2half2_rn(x, y);
    return *(uint32_t*)&h;
}

// ---------------- converts ---------------------------------------------------
__global__ __launch_bounds__(256)
void convert_x(const float* __restrict__ in, __nv_bfloat16* __restrict__ hi,
               __nv_bfloat16* __restrict__ lo, __half* __restrict__ x16)
{
    int i = (blockIdx.x * blockDim.x + threadIdx.x) * 4;
    float4 v = *(const float4*)(in + i);
    __nv_bfloat162 h0, h1, l0, l1;
    split2(v.x, h0.x, l0.x); split2(v.y, h0.y, l0.y);
    split2(v.z, h1.x, l1.x); split2(v.w, h1.y, l1.y);
    *(__nv_bfloat162*)&hi[i]     = h0;  *(__nv_bfloat162*)&hi[i + 2] = h1;
    *(__nv_bfloat162*)&lo[i]     = l0;  *(__nv_bfloat162*)&lo[i + 2] = l1;
    *(uint32_t*)&x16[i]     = packh2(v.x, v.y);
    *(uint32_t*)&x16[i + 2] = packh2(v.z, v.w);
}

__global__ __launch_bounds__(256)
void convert_w(const float* __restrict__ w0, const float* __restrict__ w1,
               const float* __restrict__ w2, const float* __restrict__ w3,
               __nv_bfloat16* __restrict__ whi, __nv_bfloat16* __restrict__ wlo,
               __half* __restrict__ wv16, __half* __restrict__ wo16)
{
    int z = blockIdx.y;
    const float* src = (z == 0) ? w0 : (z == 1) ? w1 : (z == 2) ? w2 : w3;
    int i = (blockIdx.x * blockDim.x + threadIdx.x) * 4;
    float4 v = *(const float4*)(src + i);
    if (z < 2) {
        __nv_bfloat162 h0, h1, l0, l1;
        split2(v.x, h0.x, l0.x); split2(v.y, h0.y, l0.y);
        split2(v.z, h1.x, l1.x); split2(v.w, h1.y, l1.y);
        __nv_bfloat16* hi = whi + (size_t)z * WN;
        __nv_bfloat16* lo = wlo + (size_t)z * WN;
        *(__nv_bfloat162*)&hi[i]     = h0;  *(__nv_bfloat162*)&hi[i + 2] = h1;
        *(__nv_bfloat162*)&lo[i]     = l0;  *(__nv_bfloat162*)&lo[i + 2] = l1;
    } else {
        __half* dst = (z == 2) ? wv16 : wo16;
        *(uint32_t*)&dst[i]     = packh2(v.x, v.y);
        *(uint32_t*)&dst[i + 2] = packh2(v.z, v.w);
    }
}

__global__ __launch_bounds__(256)
void convert_vt(const float* __restrict__ V, __half* __restrict__ vt)
{
    __shared__ float t[32][33];
    int bh = blockIdx.z, b = bh >> 4, h = bh & 15;
    int s0 = blockIdx.x * 32, d0 = blockIdx.y * 32;
    int lx = threadIdx.x & 31, ly = threadIdx.x >> 5;
#pragma unroll
    for (int i = 0; i < 4; i++) {
        int sl = ly + i * 8;
        t[sl][lx] = V[(size_t)(b * SEQ + s0 + sl) * DMODEL + h * DK + d0 + lx];
    }
    __syncthreads();
#pragma unroll
    for (int i = 0; i < 4; i++) {
        int dl = ly + i * 8;
        vt[(size_t)(bh * DK + d0 + dl) * SEQ + s0 + lx] = __float2half_rn(t[lx][dl]);
    }
}

// ---------------- Q,K GEMM (bf16x3 + fused RoPE, grid.z in {0,1}) ------------
#define NKIT (DMODEL / 32)
#define PLE  (128 * 40)
#define STGE (4 * PLE)

__global__ __launch_bounds__(256, 2)
void gemm_qk(const __nv_bfloat16* __restrict__ Ahi, const __nv_bfloat16* __restrict__ Alo,
             const __nv_bfloat16* __restrict__ Whi, const __nv_bfloat16* __restrict__ Wlo,
             const float* __restrict__ b0, const float* __restrict__ b1,
             __nv_bfloat16* __restrict__ qh, __nv_bfloat16* __restrict__ ql,
             __nv_bfloat16* __restrict__ kh, __nv_bfloat16* __restrict__ kl)
{
    extern __shared__ __nv_bfloat16 sm[];
    const int tid = threadIdx.x, lane = tid & 31, wid = tid >> 5;
    const int wm = wid & 3, wn = wid >> 2;
    const int m0 = blockIdx.y * 128, n0 = blockIdx.x * 128;
    const int bz = blockIdx.z;
    const uint32_t sb = smem_u32(sm);
    const __nv_bfloat16* srcs[4] = {Ahi, Alo,
                                    Whi + (size_t)bz * WN, Wlo + (size_t)bz * WN};
    const float* bias = bz ? b1 : b0;

    auto issue = [&](int kt, int stg) {
        int kofs = kt * 32;
#pragma unroll
        for (int i = 0; i < 8; i++) {
            int idx = tid + i * 256;
            int plane = idx >> 9, rem = idx & 511;
            int row = rem >> 2, ch = (rem & 3) * 8;
            int grow = (plane < 2 ? m0 : n0) + row;
            cpasync16(sb + (stg * STGE + plane * PLE + row * 40 + ch) * 2,
                      srcs[plane] + (size_t)grow * DMODEL + kofs + ch);
        }
    };

    float acc[2][8][4];
#pragma unroll
    for (int a = 0; a < 2; a++)
#pragma unroll
        for (int b = 0; b < 8; b++)
#pragma unroll
            for (int c = 0; c < 4; c++) acc[a][b][c] = 0.f;

    issue(0, 0); CP_COMMIT;

    for (int kt = 0; kt < NKIT; kt++) {
        cp_wait<0>();
        __syncthreads();
        if (kt + 1 < NKIT) { issue(kt + 1, (kt + 1) & 1); CP_COMMIT; }
        uint32_t s0 = sb + ((kt & 1) * STGE) * 2;

#pragma unroll
        for (int ks = 0; ks < 32; ks += 16) {
            uint32_t ah[2][4], al[2][4];
#pragma unroll
            for (int mt = 0; mt < 2; mt++) {
                int ar = wm * 32 + mt * 16 + (lane & 15);
                int ac = ks + ((lane >> 4) << 3);
                uint32_t off = (uint32_t)(ar * 40 + ac) * 2;
                ldmx4(ah[mt][0], ah[mt][1], ah[mt][2], ah[mt][3], s0 + off);
                ldmx4(al[mt][0], al[mt][1], al[mt][2], al[mt][3], s0 + PLE * 2 + off);
            }
#pragma unroll
            for (int np = 0; np < 4; np++) {
                int br = wn * 64 + np * 16 + ((lane >> 4) << 3) + (lane & 7);
                int bc = ks + (((lane >> 3) & 1) << 3);
                uint32_t off = (uint32_t)(br * 40 + bc) * 2;
                uint32_t h0, h1, h2, h3, q0, q1, q2, q3;
                ldmx4(h0, h1, h2, h3, s0 + PLE * 4 + off);
                ldmx4(q0, q1, q2, q3, s0 + PLE * 6 + off);
#pragma unroll
                for (int mt = 0; mt < 2; mt++) {
                    float* c0 = acc[mt][2 * np];
                    float* c1 = acc[mt][2 * np + 1];
                    mma_bf(c0, ah[mt][0], ah[mt][1], ah[mt][2], ah[mt][3], h0, h1);
                    mma_bf(c0, ah[mt][0], ah[mt][1], ah[mt][2], ah[mt][3], q0, q1);
                    mma_bf(c0, al[mt][0], al[mt][1], al[mt][2], al[mt][3], h0, h1);
                    mma_bf(c1, ah[mt][0], ah[mt][1], ah[mt][2], ah[mt][3], h2, h3);
                    mma_bf(c1, ah[mt][0], ah[mt][1], ah[mt][2], ah[mt][3], q2, q3);
                    mma_bf(c1, al[mt][0], al[mt][1], al[mt][2], al[mt][3], h2, h3);
                }
            }
        }
        __syncthreads();
    }

    const float ropescale = (bz == 0) ? 0.08838834764831843f : 1.0f;
    __nv_bfloat16* Chi = (bz == 0) ? qh : kh;
    __nv_bfloat16* Clo = (bz == 0) ? ql : kl;

#pragma unroll
    for (int mt = 0; mt < 2; mt++) {
        int r = m0 + wm * 32 + mt * 16 + (lane >> 2);
        int s_pos0 = r & (SEQ - 1);
#pragma unroll
        for (int nt = 0; nt < 8; nt++) {
            int gc = n0 + wn * 64 + nt * 8 + (lane & 3) * 2;
            float bb0 = bias[gc], bb1 = bias[gc + 1];
            float e0 = acc[mt][nt][0] + bb0, o0 = acc[mt][nt][1] + bb1;
            float e1 = acc[mt][nt][2] + bb0, o1 = acc[mt][nt][3] + bb1;
            int i = (gc & (DK - 1)) >> 1;
            float inv_freq = powf(10000.0f, -((float)(2 * i)) / 128.0f);
            float c0r, s0r, c1r, s1r;
            sincosf((float)s_pos0 * inv_freq, &s0r, &c0r);
            sincosf((float)(s_pos0 + 8) * inv_freq, &s1r, &c1r);
            float re0 = (e0 * c0r - o0 * s0r) * ropescale;
            float ro0 = (e0 * s0r + o0 * c0r) * ropescale;
            float re1 = (e1 * c1r - o1 * s1r) * ropescale;
            float ro1 = (e1 * s1r + o1 * c1r) * ropescale;
            uint32_t h0p, l0p, h1p, l1p;
            splitpack(re0, ro0, h0p, l0p);
            splitpack(re1, ro1, h1p, l1p);
            *(uint32_t*)&Chi[(size_t)r * DMODEL + gc] = h0p;
            *(uint32_t*)&Clo[(size_t)r * DMODEL + gc] = l0p;
            *(uint32_t*)&Chi[(size_t)(r + 8) * DMODEL + gc] = h1p;
            *(uint32_t*)&Clo[(size_t)(r + 8) * DMODEL + gc] = l1p;
        }
    }
}

// ---------------- fp16 single-mma GEMM (V projection & output projection) ----
#define PLE16  (128 * 40)
#define STGE16 (2 * PLE16)

__global__ __launch_bounds__(256, 2)
void gemm_f16(const __half* __restrict__ A, const __half* __restrict__ B,
              const float* __restrict__ bias, float* __restrict__ C)
{
    extern __shared__ __half smh[];
    const int tid = threadIdx.x, lane = tid & 31, wid = tid >> 5;
    const int wm = wid & 3, wn = wid >> 2;
    const int m0 = blockIdx.y * 128, n0 = blockIdx.x * 128;
    const uint32_t sb = smem_u32(smh);

    auto issue = [&](int kt, int stg) {
        int kofs = kt * 32;
#pragma unroll
        for (int i = 0; i < 4; i++) {
            int idx = tid + i * 256;
            int plane = idx >> 9, rem = idx & 511;
            int row = rem >> 2, ch = (rem & 3) * 8;
            const __half* src = plane ? (B + (size_t)(n0 + row) * DMODEL + kofs + ch)
                                      : (A + (size_t)(m0 + row) * DMODEL + kofs + ch);
            cpasync16(sb + (stg * STGE16 + plane * PLE16 + row * 40 + ch) * 2, src);
        }
    };

    float acc[2][8][4];
#pragma unroll
    for (int a = 0; a < 2; a++)
#pragma unroll
        for (int b = 0; b < 8; b++)
#pragma unroll
            for (int c = 0; c < 4; c++) acc[a][b][c] = 0.f;

    issue(0, 0); CP_COMMIT;

    for (int kt = 0; kt < NKIT; kt++) {
        cp_wait<0>();
        __syncthreads();
        if (kt + 1 < NKIT) { issue(kt + 1, (kt + 1) & 1); CP_COMMIT; }
        uint32_t s0 = sb + ((kt & 1) * STGE16) * 2;

#pragma unroll
        for (int ks = 0; ks < 32; ks += 16) {
            uint32_t av[2][4];
#pragma unroll
            for (int mt = 0; mt < 2; mt++) {
                int ar = wm * 32 + mt * 16 + (lane & 15);
                int ac = ks + ((lane >> 4) << 3);
                uint32_t off = (uint32_t)(ar * 40 + ac) * 2;
                ldmx4(av[mt][0], av[mt][1], av[mt][2], av[mt][3], s0 + off);
            }
#pragma unroll
            for (int np = 0; np < 4; np++) {
                int br = wn * 64 + np * 16 + ((lane >> 4) << 3) + (lane & 7);
                int bc = ks + (((lane >> 3) & 1) << 3);
                uint32_t off = (uint32_t)(br * 40 + bc) * 2;
                uint32_t b0, b1, b2, b3;
                ldmx4(b0, b1, b2, b3, s0 + PLE16 * 2 + off);
#pragma unroll
                for (int mt = 0; mt < 2; mt++) {
                    mma_f16(acc[mt][2 * np],     av[mt][0], av[mt][1], av[mt][2], av[mt][3], b0, b1);
                    mma_f16(acc[mt][2 * np + 1], av[mt][0], av[mt][1], av[mt][2], av[mt][3], b2, b3);
                }
            }
        }
        __syncthreads();
    }

#pragma unroll
    for (int mt = 0; mt < 2; mt++) {
        int r = m0 + wm * 32 + mt * 16 + (lane >> 2);
#pragma unroll
        for (int nt = 0; nt < 8; nt++) {
            int gc = n0 + wn * 64 + nt * 8 + (lane & 3) * 2;
            float bb0 = bias[gc], bb1 = bias[gc + 1];
            float2 v0 = {acc[mt][nt][0] + bb0, acc[mt][nt][1] + bb1};
            float2 v1 = {acc[mt][nt][2] + bb0, acc[mt][nt][3] + bb1};
            *(float2*)&C[(size_t)r * DMODEL + gc] = v0;
            *(float2*)&C[(size_t)(r + 8) * DMODEL + gc] = v1;
        }
    }
}

// ---------------- Flash attention: QK bf16x3, PV fp16 single -----------------
#define FQH 0
#define FQL 8704
#define FKH 17408
#define FKL 26112
#define FV  34816
#define FTOT 44032

__global__ __launch_bounds__(128, 2)
void flash_mma(const __nv_bfloat16* __restrict__ Qh, const __nv_bfloat16* __restrict__ Ql,
               const __nv_bfloat16* __restrict__ Kh, const __nv_bfloat16* __restrict__ Kl,
               const __half* __restrict__ V16, __half* __restrict__ A16)
{
    extern __shared__ __nv_bfloat16 sm[];
    const uint32_t sb = smem_u32(sm);
    const int tid = threadIdx.x, lane = tid & 31, warp = tid >> 5;
    const int qblk = blockIdx.x, bh = blockIdx.y;
    const int b = bh >> 4, h = bh & 15, q0 = qblk * 64;
    const int hofs = h * DK;
    const size_t qrow0 = (size_t)(b * SEQ + q0);
    const __half* vtbase = V16 + (size_t)bh * DK * SEQ;

#pragma unroll
    for (int i = 0; i < 8; i++) {
        int idx = tid + i * 128;
        int r = idx >> 4, c = (idx & 15) * 8;
        cpasync16(sb + (FQH + r * 136 + c) * 2, Qh + (qrow0 + r) * DMODEL + hofs + c);
        cpasync16(sb + (FQL + r * 136 + c) * 2, Ql + (qrow0 + r) * DMODEL + hofs + c);
    }
    CP_COMMIT;

    float o[16][4];
#pragma unroll
    for (int t = 0; t < 16; t++)
#pragma unroll
        for (int e = 0; e < 4; e++) o[t][e] = 0.f;
    float m0v = -INFINITY, m1v = -INFINITY, l0v = 0.f, l1v = 0.f;

    for (int jb = 0; jb <= qblk; ++jb) {
        const int k0 = jb * 64;
        const size_t krow0 = (size_t)(b * SEQ + k0);
#pragma unroll
        for (int i = 0; i < 8; i++) {
            int idx = tid + i * 128;
            int r = idx >> 4, c = (idx & 15) * 8;
            cpasync16(sb + (FKH + r * 136 + c) * 2, Kh + (krow0 + r) * DMODEL + hofs + c);
            cpasync16(sb + (FKL + r * 136 + c) * 2, Kl + (krow0 + r) * DMODEL + hofs + c);
        }
#pragma unroll
        for (int i = 0; i < 8; i++) {
            int idx = tid + i * 128;
            int d = idx >> 3, c = (idx & 7) * 8;
            cpasync16(sb + (FV + d * 72 + c) * 2, vtbase + (size_t)d * SEQ + k0 + c);
        }
        CP_COMMIT; cp_wait<0>();
        __syncthreads();

        float s[8][4];
#pragma unroll
        for (int t = 0; t < 8; t++)
#pragma unroll
            for (int e = 0; e < 4; e++) s[t][e] = 0.f;

#pragma unroll
        for (int kc = 0; kc < 8; kc++) {
            int ar = warp * 16 + (lane & 15);
            int ac = kc * 16 + ((lane >> 4) << 3);
            uint32_t aoff = (uint32_t)(ar * 136 + ac) * 2;
            uint32_t qh0, qh1, qh2, qh3, ql0, ql1, ql2, ql3;
            ldmx4(qh0, qh1, qh2, qh3, sb + FQH * 2 + aoff);
            ldmx4(ql0, ql1, ql2, ql3, sb + FQL * 2 + aoff);
#pragma unroll
            for (int np = 0; np < 4; np++) {
                int br = np * 16 + ((lane >> 4) << 3) + (lane & 7);
                int bc = kc * 16 + (((lane >> 3) & 1) << 3);
                uint32_t boff = (uint32_t)(br * 136 + bc) * 2;
                uint32_t kh0, kh1, kh2, kh3, kl0, kl1, kl2, kl3;
                ldmx4(kh0, kh1, kh2, kh3, sb + FKH * 2 + boff);
                ldmx4(kl0, kl1, kl2, kl3, sb + FKL * 2 + boff);
                mma_bf(s[2 * np],     qh0, qh1, qh2, qh3, kh0, kh1);
                mma_bf(s[2 * np],     ql0, ql1, ql2, ql3, kh0, kh1);
                mma_bf(s[2 * np],     qh0, qh1, qh2, qh3, kl0, kl1);
                mma_bf(s[2 * np + 1], qh0, qh1, qh2, qh3, kh2, kh3);
                mma_bf(s[2 * np + 1], ql0, ql1, ql2, ql3, kh2, kh3);
                mma_bf(s[2 * np + 1], qh0, qh1, qh2, qh3, kl2, kl3);
            }
        }

        if (jb == qblk) {
            int r0 = q0 + warp * 16 + (lane >> 2);
#pragma unroll
            for (int t = 0; t < 8; t++) {
                int c0 = k0 + t * 8 + 2 * (lane & 3);
                if (c0 > r0)     s[t][0] = -INFINITY;
                if (c0 + 1 > r0) s[t][1] = -INFINITY;
                if (c0 > r0 + 8)     s[t][2] = -INFINITY;
                if (c0 + 1 > r0 + 8) s[t][3] = -INFINITY;
            }
        }

        float mx0 = -INFINITY, mx1 = -INFINITY;
#pragma unroll
        for (int t = 0; t < 8; t++) {
            mx0 = fmaxf(mx0, fmaxf(s[t][0], s[t][1]));
            mx1 = fmaxf(mx1, fmaxf(s[t][2], s[t][3]));
        }
        mx0 = fmaxf(mx0, __shfl_xor_sync(0xffffffffu, mx0, 1));
        mx0 = fmaxf(mx0, __shfl_xor_sync(0xffffffffu, mx0, 2));
        mx1 = fmaxf(mx1, __shfl_xor_sync(0xffffffffu, mx1, 1));
        mx1 = fmaxf(mx1, __shfl_xor_sync(0xffffffffu, mx1, 2));
        float mn0 = fmaxf(m0v, mx0), mn1 = fmaxf(m1v, mx1);
        float sc0 = __expf(m0v - mn0), sc1 = __expf(m1v - mn1);
        float sum0 = 0.f, sum1 = 0.f;
#pragma unroll
        for (int t = 0; t < 8; t++) {
            s[t][0] = __expf(s[t][0] - mn0); sum0 += s[t][0];
            s[t][1] = __expf(s[t][1] - mn0); sum0 += s[t][1];
            s[t][2] = __expf(s[t][2] - mn1); sum1 += s[t][2];
            s[t][3] = __expf(s[t][3] - mn1); sum1 += s[t][3];
        }
        sum0 += __shfl_xor_sync(0xffffffffu, sum0, 1);
        sum0 += __shfl_xor_sync(0xffffffffu, sum0, 2);
        sum1 += __shfl_xor_sync(0xffffffffu, sum1, 1);
        sum1 += __shfl_xor_sync(0xffffffffu, sum1, 2);
        l0v = l0v * sc0 + sum0; m0v = mn0;
        l1v = l1v * sc1 + sum1; m1v = mn1;

#pragma unroll
        for (int t = 0; t < 16; t++) {
            o[t][0] *= sc0; o[t][1] *= sc0; o[t][2] *= sc1; o[t][3] *= sc1;
        }

        // P @ V, fp16 single
#pragma unroll
        for (int kc = 0; kc < 4; kc++) {
            uint32_t p0 = packh2(s[2 * kc][0],     s[2 * kc][1]);
            uint32_t p1 = packh2(s[2 * kc][2],     s[2 * kc][3]);
            uint32_t p2 = packh2(s[2 * kc + 1][0], s[2 * kc + 1][1]);
            uint32_t p3 = packh2(s[2 * kc + 1][2], s[2 * kc + 1][3]);
#pragma unroll
            for (int np = 0; np < 8; np++) {
                int br = np * 16 + ((lane >> 4) << 3) + (lane & 7);
                int bc = kc * 16 + (((lane >> 3) & 1) << 3);
                uint32_t boff = (uint32_t)(br * 72 + bc) * 2;
                uint32_t v0, v1, v2, v3;
                ldmx4(v0, v1, v2, v3, sb + FV * 2 + boff);
                mma_f16(o[2 * np],     p0, p1, p2, p3, v0, v1);
                mma_f16(o[2 * np + 1], p0, p1, p2, p3, v2, v3);
            }
        }
        __syncthreads();
    }

    float inv0 = 1.f / l0v, inv1 = 1.f / l1v;
    int r0 = b * SEQ + q0 + warp * 16 + (lane >> 2);
#pragma unroll
    for (int t = 0; t < 16; t++) {
        int gc = hofs + t * 8 + 2 * (lane & 3);
        *(uint32_t*)&A16[(size_t)r0 * DMODEL + gc] = packh2(o[t][0] * inv0, o[t][1] * inv0);
        *(uint32_t*)&A16[(size_t)(r0 + 8) * DMODEL + gc] = packh2(o[t][2] * inv1, o[t][3] * inv1);
    }
}

// ---------------- launch ------------------------------------------------------
extern "C" void kernel_launch(void* const* d_in, const int* in_sizes, int n_in,
                              void* d_out, int out_size)
{
    const float* x    = (const float*)d_in[0];
    const float* w[4] = {(const float*)d_in[1], (const float*)d_in[3],
                         (const float*)d_in[5], (const float*)d_in[7]};
    const float* bi[4] = {(const float*)d_in[2], (const float*)d_in[4],
                          (const float*)d_in[6], (const float*)d_in[8]};
    float* out = (float*)d_out;

    float* vb;
    cudaGetSymbolAddress((void**)&vb, g_V);
    __nv_bfloat16 *xh, *xl, *wh, *wl, *qh, *ql, *kh, *kl;
    __half *x16, *wv16, *wo16, *a16, *vt16;
    cudaGetSymbolAddress((void**)&xh, g_xhi);  cudaGetSymbolAddress((void**)&xl, g_xlo);
    cudaGetSymbolAddress((void**)&wh, g_whi);  cudaGetSymbolAddress((void**)&wl, g_wlo);
    cudaGetSymbolAddress((void**)&qh, g_qhi);  cudaGetSymbolAddress((void**)&ql, g_qlo);
    cudaGetSymbolAddress((void**)&kh, g_khi);  cudaGetSymbolAddress((void**)&kl, g_klo);
    cudaGetSymbolAddress((void**)&x16, g_x16);
    cudaGetSymbolAddress((void**)&wv16, g_wv16);
    cudaGetSymbolAddress((void**)&wo16, g_wo16);
    cudaGetSymbolAddress((void**)&a16, g_a16);
    cudaGetSymbolAddress((void**)&vt16, g_vt16);

    convert_x<<<ROWS * DMODEL / 1024, 256>>>(x, xh, xl, x16);
    convert_w<<<dim3(WN / 1024, 4), 256>>>(w[0], w[1], w[2], w[3], wh, wl, wv16, wo16);

    size_t gsmem = 2 * STGE * sizeof(__nv_bfloat16);
    cudaFuncSetAttribute(gemm_qk, cudaFuncAttributeMaxDynamicSharedMemorySize,
                         (int)gsmem);
    gemm_qk<<<dim3(DMODEL / 128, ROWS / 128, 2), 256, gsmem>>>(
        xh, xl, wh, wl, bi[0], bi[1], qh, ql, kh, kl);

    size_t g16smem = 2 * STGE16 * sizeof(__half);
    cudaFuncSetAttribute(gemm_f16, cudaFuncAttributeMaxDynamicSharedMemorySize,
                         (int)g16smem);
    gemm_f16<<<dim3(DMODEL / 128, ROWS / 128), 256, g16smem>>>(x16, wv16, bi[2], vb);

    convert_vt<<<dim3(SEQ / 32, DK / 32, BATCH * NHEADS), 256>>>(vb, vt16);

    size_t fsmem = FTOT * sizeof(__nv_bfloat16);
    cudaFuncSetAttribute(flash_mma, cudaFuncAttributeMaxDynamicSharedMemorySize,
                         (int)fsmem);
    flash_mma<<<dim3(SEQ / 64, BATCH * NHEADS), 128, fsmem>>>(
        qh, ql, kh, kl, vt16, a16);

    gemm_f16<<<dim3(DMODEL / 128, ROWS / 128), 256, g16smem>>>(a16, wo16, bi[3], out);
}

// round 10
// speedup vs baseline: 6.5410x; 1.6275x over previous
#include <cuda_runtime.h>
#include <cuda_fp16.h>
#include <math.h>
#include <stdint.h>

#define BATCH   2
#define SEQ     2048
#define DMODEL  2048
#define NHEADS  16
#define DK      128
#define ROWS    (BATCH * SEQ)
#define WN      (DMODEL * DMODEL)

// ---------------- scratch ----------------------------------------------------
__device__ float  g_V[ROWS * DMODEL];
__device__ __half g_x16[ROWS * DMODEL];
__device__ __half g_w16[3][WN];            // wq, wk, wv
__device__ __half g_wo16[WN];
__device__ __half g_q16[ROWS * DMODEL];
__device__ __half g_k16[ROWS * DMODEL];
__device__ __half g_vt16[ROWS * DMODEL];   // [bh][d][s]
__device__ __half g_a16[ROWS * DMODEL];

// ---------------- helpers ----------------------------------------------------
__device__ __forceinline__ uint32_t smem_u32(const void* p) {
    return (uint32_t)__cvta_generic_to_shared(p);
}
__device__ __forceinline__ void ldmx4(uint32_t& r0, uint32_t& r1, uint32_t& r2,
                                      uint32_t& r3, uint32_t a) {
    asm volatile("ldmatrix.sync.aligned.m8n8.x4.shared.b16 {%0,%1,%2,%3},[%4];"
                 : "=r"(r0), "=r"(r1), "=r"(r2), "=r"(r3) : "r"(a));
}
__device__ __forceinline__ void mma_f16(float* c, uint32_t a0, uint32_t a1,
                                        uint32_t a2, uint32_t a3,
                                        uint32_t b0, uint32_t b1) {
    asm volatile(
        "mma.sync.aligned.m16n8k16.row.col.f32.f16.f16.f32 "
        "{%0,%1,%2,%3},{%4,%5,%6,%7},{%8,%9},{%0,%1,%2,%3};"
        : "+f"(c[0]), "+f"(c[1]), "+f"(c[2]), "+f"(c[3])
        : "r"(a0), "r"(a1), "r"(a2), "r"(a3), "r"(b0), "r"(b1));
}
__device__ __forceinline__ void cpasync16(uint32_t dst, const void* src) {
    asm volatile("cp.async.cg.shared.global [%0],[%1],16;" :: "r"(dst), "l"(src));
}
#define CP_COMMIT asm volatile("cp.async.commit_group;")
template<int N> __device__ __forceinline__ void cp_wait() {
    asm volatile("cp.async.wait_group %0;" :: "n"(N));
}
__device__ __forceinline__ uint32_t packh2(float x, float y) {
    __half2 h = __floats2half2_rn(x, y);
    return *(uint32_t*)&h;
}

// ---------------- converts ---------------------------------------------------
__global__ __launch_bounds__(256)
void convert_x(const float* __restrict__ in, __half* __restrict__ x16)
{
    int i = (blockIdx.x * blockDim.x + threadIdx.x) * 4;
    float4 v = *(const float4*)(in + i);
    *(uint32_t*)&x16[i]     = packh2(v.x, v.y);
    *(uint32_t*)&x16[i + 2] = packh2(v.z, v.w);
}

__global__ __launch_bounds__(256)
void convert_w(const float* __restrict__ w0, const float* __restrict__ w1,
               const float* __restrict__ w2, const float* __restrict__ w3,
               __half* __restrict__ wqkv, __half* __restrict__ wo16)
{
    int z = blockIdx.y;
    const float* src = (z == 0) ? w0 : (z == 1) ? w1 : (z == 2) ? w2 : w3;
    __half* dst = (z < 3) ? (wqkv + (size_t)z * WN) : wo16;
    int i = (blockIdx.x * blockDim.x + threadIdx.x) * 4;
    float4 v = *(const float4*)(src + i);
    *(uint32_t*)&dst[i]     = packh2(v.x, v.y);
    *(uint32_t*)&dst[i + 2] = packh2(v.z, v.w);
}

__global__ __launch_bounds__(256)
void convert_vt(const float* __restrict__ V, __half* __restrict__ vt)
{
    __shared__ float t[32][33];
    int bh = blockIdx.z, b = bh >> 4, h = bh & 15;
    int s0 = blockIdx.x * 32, d0 = blockIdx.y * 32;
    int lx = threadIdx.x & 31, ly = threadIdx.x >> 5;
#pragma unroll
    for (int i = 0; i < 4; i++) {
        int sl = ly + i * 8;
        t[sl][lx] = V[(size_t)(b * SEQ + s0 + sl) * DMODEL + h * DK + d0 + lx];
    }
    __syncthreads();
#pragma unroll
    for (int i = 0; i < 4; i++) {
        int dl = ly + i * 8;
        vt[(size_t)(bh * DK + d0 + dl) * SEQ + s0 + lx] = __float2half_rn(t[lx][dl]);
    }
}

// ---------------- fp16 GEMM common mainloop ----------------------------------
#define NKIT   (DMODEL / 32)
#define PLE16  (128 * 40)
#define STGE16 (2 * PLE16)

// z = 0: Q (RoPE + 1/sqrt(dk), fp16 out) | 1: K (RoPE, fp16 out) | 2: V (fp32 out)
__global__ __launch_bounds__(256, 2)
void gemm_proj(const __half* __restrict__ A, const __half* __restrict__ W,
               const float* __restrict__ b0, const float* __restrict__ b1,
               const float* __restrict__ b2,
               __half* __restrict__ Q16, __half* __restrict__ K16,
               float* __restrict__ Vf)
{
    extern __shared__ __half smh[];
    const int tid = threadIdx.x, lane = tid & 31, wid = tid >> 5;
    const int wm = wid & 3, wn = wid >> 2;
    const int m0 = blockIdx.y * 128, n0 = blockIdx.x * 128;
    const int bz = blockIdx.z;
    const uint32_t sb = smem_u32(smh);
    const __half* B = W + (size_t)bz * WN;
    const float* bias = (bz == 0) ? b0 : (bz == 1) ? b1 : b2;

    auto issue = [&](int kt, int stg) {
        int kofs = kt * 32;
#pragma unroll
        for (int i = 0; i < 4; i++) {
            int idx = tid + i * 256;
            int plane = idx >> 9, rem = idx & 511;
            int row = rem >> 2, ch = (rem & 3) * 8;
            const __half* src = plane ? (B + (size_t)(n0 + row) * DMODEL + kofs + ch)
                                      : (A + (size_t)(m0 + row) * DMODEL + kofs + ch);
            cpasync16(sb + (stg * STGE16 + plane * PLE16 + row * 40 + ch) * 2, src);
        }
    };

    float acc[2][8][4];
#pragma unroll
    for (int a = 0; a < 2; a++)
#pragma unroll
        for (int b = 0; b < 8; b++)
#pragma unroll
            for (int c = 0; c < 4; c++) acc[a][b][c] = 0.f;

    issue(0, 0); CP_COMMIT;

    for (int kt = 0; kt < NKIT; kt++) {
        cp_wait<0>();
        __syncthreads();
        if (kt + 1 < NKIT) { issue(kt + 1, (kt + 1) & 1); CP_COMMIT; }
        uint32_t s0 = sb + ((kt & 1) * STGE16) * 2;

#pragma unroll
        for (int ks = 0; ks < 32; ks += 16) {
            uint32_t av[2][4];
#pragma unroll
            for (int mt = 0; mt < 2; mt++) {
                int ar = wm * 32 + mt * 16 + (lane & 15);
                int ac = ks + ((lane >> 4) << 3);
                uint32_t off = (uint32_t)(ar * 40 + ac) * 2;
                ldmx4(av[mt][0], av[mt][1], av[mt][2], av[mt][3], s0 + off);
            }
#pragma unroll
            for (int np = 0; np < 4; np++) {
                int br = wn * 64 + np * 16 + ((lane >> 4) << 3) + (lane & 7);
                int bc = ks + (((lane >> 3) & 1) << 3);
                uint32_t off = (uint32_t)(br * 40 + bc) * 2;
                uint32_t bv0, bv1, bv2, bv3;
                ldmx4(bv0, bv1, bv2, bv3, s0 + PLE16 * 2 + off);
#pragma unroll
                for (int mt = 0; mt < 2; mt++) {
                    mma_f16(acc[mt][2 * np],     av[mt][0], av[mt][1], av[mt][2], av[mt][3], bv0, bv1);
                    mma_f16(acc[mt][2 * np + 1], av[mt][0], av[mt][1], av[mt][2], av[mt][3], bv2, bv3);
                }
            }
        }
        __syncthreads();
    }

#pragma unroll
    for (int mt = 0; mt < 2; mt++) {
        int r = m0 + wm * 32 + mt * 16 + (lane >> 2);
        int s_pos0 = r & (SEQ - 1);
#pragma unroll
        for (int nt = 0; nt < 8; nt++) {
            int gc = n0 + wn * 64 + nt * 8 + (lane & 3) * 2;
            float bb0 = bias[gc], bb1 = bias[gc + 1];
            float e0 = acc[mt][nt][0] + bb0, o0 = acc[mt][nt][1] + bb1;
            float e1 = acc[mt][nt][2] + bb0, o1 = acc[mt][nt][3] + bb1;
            if (bz == 2) {
                float2 v0 = {e0, o0}, v1 = {e1, o1};
                *(float2*)&Vf[(size_t)r * DMODEL + gc] = v0;
                *(float2*)&Vf[(size_t)(r + 8) * DMODEL + gc] = v1;
            } else {
                const float ropescale = (bz == 0) ? 0.08838834764831843f : 1.0f;
                __half* C16 = (bz == 0) ? Q16 : K16;
                int i = (gc & (DK - 1)) >> 1;
                float inv_freq = powf(10000.0f, -((float)(2 * i)) / 128.0f);
                float c0r, s0r, c1r, s1r;
                sincosf((float)s_pos0 * inv_freq, &s0r, &c0r);
                sincosf((float)(s_pos0 + 8) * inv_freq, &s1r, &c1r);
                float re0 = (e0 * c0r - o0 * s0r) * ropescale;
                float ro0 = (e0 * s0r + o0 * c0r) * ropescale;
                float re1 = (e1 * c1r - o1 * s1r) * ropescale;
                float ro1 = (e1 * s1r + o1 * c1r) * ropescale;
                *(uint32_t*)&C16[(size_t)r * DMODEL + gc] = packh2(re0, ro0);
                *(uint32_t*)&C16[(size_t)(r + 8) * DMODEL + gc] = packh2(re1, ro1);
            }
        }
    }
}

// ---------------- fp16 GEMM (output projection, fp32 out) --------------------
__global__ __launch_bounds__(256, 2)
void gemm_f16(const __half* __restrict__ A, const __half* __restrict__ B,
              const float* __restrict__ bias, float* __restrict__ C)
{
    extern __shared__ __half smh[];
    const int tid = threadIdx.x, lane = tid & 31, wid = tid >> 5;
    const int wm = wid & 3, wn = wid >> 2;
    const int m0 = blockIdx.y * 128, n0 = blockIdx.x * 128;
    const uint32_t sb = smem_u32(smh);

    auto issue = [&](int kt, int stg) {
        int kofs = kt * 32;
#pragma unroll
        for (int i = 0; i < 4; i++) {
            int idx = tid + i * 256;
            int plane = idx >> 9, rem = idx & 511;
            int row = rem >> 2, ch = (rem & 3) * 8;
            const __half* src = plane ? (B + (size_t)(n0 + row) * DMODEL + kofs + ch)
                                      : (A + (size_t)(m0 + row) * DMODEL + kofs + ch);
            cpasync16(sb + (stg * STGE16 + plane * PLE16 + row * 40 + ch) * 2, src);
        }
    };

    float acc[2][8][4];
#pragma unroll
    for (int a = 0; a < 2; a++)
#pragma unroll
        for (int b = 0; b < 8; b++)
#pragma unroll
            for (int c = 0; c < 4; c++) acc[a][b][c] = 0.f;

    issue(0, 0); CP_COMMIT;

    for (int kt = 0; kt < NKIT; kt++) {
        cp_wait<0>();
        __syncthreads();
        if (kt + 1 < NKIT) { issue(kt + 1, (kt + 1) & 1); CP_COMMIT; }
        uint32_t s0 = sb + ((kt & 1) * STGE16) * 2;

#pragma unroll
        for (int ks = 0; ks < 32; ks += 16) {
            uint32_t av[2][4];
#pragma unroll
            for (int mt = 0; mt < 2; mt++) {
                int ar = wm * 32 + mt * 16 + (lane & 15);
                int ac = ks + ((lane >> 4) << 3);
                uint32_t off = (uint32_t)(ar * 40 + ac) * 2;
                ldmx4(av[mt][0], av[mt][1], av[mt][2], av[mt][3], s0 + off);
            }
#pragma unroll
            for (int np = 0; np < 4; np++) {
                int br = wn * 64 + np * 16 + ((lane >> 4) << 3) + (lane & 7);
                int bc = ks + (((lane >> 3) & 1) << 3);
                uint32_t off = (uint32_t)(br * 40 + bc) * 2;
                uint32_t bv0, bv1, bv2, bv3;
                ldmx4(bv0, bv1, bv2, bv3, s0 + PLE16 * 2 + off);
#pragma unroll
                for (int mt = 0; mt < 2; mt++) {
                    mma_f16(acc[mt][2 * np],     av[mt][0], av[mt][1], av[mt][2], av[mt][3], bv0, bv1);
                    mma_f16(acc[mt][2 * np + 1], av[mt][0], av[mt][1], av[mt][2], av[mt][3], bv2, bv3);
                }
            }
        }
        __syncthreads();
    }

#pragma unroll
    for (int mt = 0; mt < 2; mt++) {
        int r = m0 + wm * 32 + mt * 16 + (lane >> 2);
#pragma unroll
        for (int nt = 0; nt < 8; nt++) {
            int gc = n0 + wn * 64 + nt * 8 + (lane & 3) * 2;
            float bb0 = bias[gc], bb1 = bias[gc + 1];
            float2 v0 = {acc[mt][nt][0] + bb0, acc[mt][nt][1] + bb1};
            float2 v1 = {acc[mt][nt][2] + bb0, acc[mt][nt][3] + bb1};
            *(float2*)&C[(size_t)r * DMODEL + gc] = v0;
            *(float2*)&C[(size_t)(r + 8) * DMODEL + gc] = v1;
        }
    }
}

// ---------------- Flash attention, all fp16 ----------------------------------
#define FQ  0
#define FK  8704
#define FV  17408
#define FTOT 26624

__global__ __launch_bounds__(128, 3)
void flash_mma(const __half* __restrict__ Q16, const __half* __restrict__ K16,
               const __half* __restrict__ V16, __half* __restrict__ A16)
{
    extern __shared__ __half smf[];
    const uint32_t sb = smem_u32(smf);
    const int tid = threadIdx.x, lane = tid & 31, warp = tid >> 5;
    const int qblk = blockIdx.x, bh = blockIdx.y;
    const int b = bh >> 4, h = bh & 15, q0 = qblk * 64;
    const int hofs = h * DK;
    const size_t qrow0 = (size_t)(b * SEQ + q0);
    const __half* vtbase = V16 + (size_t)bh * DK * SEQ;

#pragma unroll
    for (int i = 0; i < 8; i++) {
        int idx = tid + i * 128;
        int r = idx >> 4, c = (idx & 15) * 8;
        cpasync16(sb + (FQ + r * 136 + c) * 2, Q16 + (qrow0 + r) * DMODEL + hofs + c);
    }
    CP_COMMIT;

    float o[16][4];
#pragma unroll
    for (int t = 0; t < 16; t++)
#pragma unroll
        for (int e = 0; e < 4; e++) o[t][e] = 0.f;
    float m0v = -INFINITY, m1v = -INFINITY, l0v = 0.f, l1v = 0.f;

    for (int jb = 0; jb <= qblk; ++jb) {
        const int k0 = jb * 64;
        const size_t krow0 = (size_t)(b * SEQ + k0);
#pragma unroll
        for (int i = 0; i < 8; i++) {
            int idx = tid + i * 128;
            int r = idx >> 4, c = (idx & 15) * 8;
            cpasync16(sb + (FK + r * 136 + c) * 2, K16 + (krow0 + r) * DMODEL + hofs + c);
        }
#pragma unroll
        for (int i = 0; i < 8; i++) {
            int idx = tid + i * 128;
            int d = idx >> 3, c = (idx & 7) * 8;
            cpasync16(sb + (FV + d * 72 + c) * 2, vtbase + (size_t)d * SEQ + k0 + c);
        }
        CP_COMMIT; cp_wait<0>();
        __syncthreads();

        float s[8][4];
#pragma unroll
        for (int t = 0; t < 8; t++)
#pragma unroll
            for (int e = 0; e < 4; e++) s[t][e] = 0.f;

#pragma unroll
        for (int kc = 0; kc < 8; kc++) {
            int ar = warp * 16 + (lane & 15);
            int ac = kc * 16 + ((lane >> 4) << 3);
            uint32_t aoff = (uint32_t)(ar * 136 + ac) * 2;
            uint32_t q0r, q1r, q2r, q3r;
            ldmx4(q0r, q1r, q2r, q3r, sb + FQ * 2 + aoff);
#pragma unroll
            for (int np = 0; np < 4; np++) {
                int br = np * 16 + ((lane >> 4) << 3) + (lane & 7);
                int bc = kc * 16 + (((lane >> 3) & 1) << 3);
                uint32_t boff = (uint32_t)(br * 136 + bc) * 2;
                uint32_t k0r, k1r, k2r, k3r;
                ldmx4(k0r, k1r, k2r, k3r, sb + FK * 2 + boff);
                mma_f16(s[2 * np],     q0r, q1r, q2r, q3r, k0r, k1r);
                mma_f16(s[2 * np + 1], q0r, q1r, q2r, q3r, k2r, k3r);
            }
        }

        if (jb == qblk) {
            int r0 = q0 + warp * 16 + (lane >> 2);
#pragma unroll
            for (int t = 0; t < 8; t++) {
                int c0 = k0 + t * 8 + 2 * (lane & 3);
                if (c0 > r0)     s[t][0] = -INFINITY;
                if (c0 + 1 > r0) s[t][1] = -INFINITY;
                if (c0 > r0 + 8)     s[t][2] = -INFINITY;
                if (c0 + 1 > r0 + 8) s[t][3] = -INFINITY;
            }
        }

        float mx0 = -INFINITY, mx1 = -INFINITY;
#pragma unroll
        for (int t = 0; t < 8; t++) {
            mx0 = fmaxf(mx0, fmaxf(s[t][0], s[t][1]));
            mx1 = fmaxf(mx1, fmaxf(s[t][2], s[t][3]));
        }
        mx0 = fmaxf(mx0, __shfl_xor_sync(0xffffffffu, mx0, 1));
        mx0 = fmaxf(mx0, __shfl_xor_sync(0xffffffffu, mx0, 2));
        mx1 = fmaxf(mx1, __shfl_xor_sync(0xffffffffu, mx1, 1));
        mx1 = fmaxf(mx1, __shfl_xor_sync(0xffffffffu, mx1, 2));
        float mn0 = fmaxf(m0v, mx0), mn1 = fmaxf(m1v, mx1);
        float sc0 = __expf(m0v - mn0), sc1 = __expf(m1v - mn1);
        float sum0 = 0.f, sum1 = 0.f;
#pragma unroll
        for (int t = 0; t < 8; t++) {
            s[t][0] = __expf(s[t][0] - mn0); sum0 += s[t][0];
            s[t][1] = __expf(s[t][1] - mn0); sum0 += s[t][1];
            s[t][2] = __expf(s[t][2] - mn1); sum1 += s[t][2];
            s[t][3] = __expf(s[t][3] - mn1); sum1 += s[t][3];
        }
        sum0 += __shfl_xor_sync(0xffffffffu, sum0, 1);
        sum0 += __shfl_xor_sync(0xffffffffu, sum0, 2);
        sum1 += __shfl_xor_sync(0xffffffffu, sum1, 1);
        sum1 += __shfl_xor_sync(0xffffffffu, sum1, 2);
        l0v = l0v * sc0 + sum0; m0v = mn0;
        l1v = l1v * sc1 + sum1; m1v = mn1;

#pragma unroll
        for (int t = 0; t < 16; t++) {
            o[t][0] *= sc0; o[t][1] *= sc0; o[t][2] *= sc1; o[t][3] *= sc1;
        }

#pragma unroll
        for (int kc = 0; kc < 4; kc++) {
            uint32_t p0 = packh2(s[2 * kc][0],     s[2 * kc][1]);
            uint32_t p1 = packh2(s[2 * kc][2],     s[2 * kc][3]);
            uint32_t p2 = packh2(s[2 * kc + 1][0], s[2 * kc + 1][1]);
            uint32_t p3 = packh2(s[2 * kc + 1][2], s[2 * kc + 1][3]);
#pragma unroll
            for (int np = 0; np < 8; np++) {
                int br = np * 16 + ((lane >> 4) << 3) + (lane & 7);
                int bc = kc * 16 + (((lane >> 3) & 1) << 3);
                uint32_t boff = (uint32_t)(br * 72 + bc) * 2;
                uint32_t v0, v1, v2, v3;
                ldmx4(v0, v1, v2, v3, sb + FV * 2 + boff);
                mma_f16(o[2 * np],     p0, p1, p2, p3, v0, v1);
                mma_f16(o[2 * np + 1], p0, p1, p2, p3, v2, v3);
            }
        }
        __syncthreads();
    }

    float inv0 = 1.f / l0v, inv1 = 1.f / l1v;
    int r0 = b * SEQ + q0 + warp * 16 + (lane >> 2);
#pragma unroll
    for (int t = 0; t < 16; t++) {
        int gc = hofs + t * 8 + 2 * (lane & 3);
        *(uint32_t*)&A16[(size_t)r0 * DMODEL + gc] = packh2(o[t][0] * inv0, o[t][1] * inv0);
        *(uint32_t*)&A16[(size_t)(r0 + 8) * DMODEL + gc] = packh2(o[t][2] * inv1, o[t][3] * inv1);
    }
}

// ---------------- launch ------------------------------------------------------
extern "C" void kernel_launch(void* const* d_in, const int* in_sizes, int n_in,
                              void* d_out, int out_size)
{
    const float* x    = (const float*)d_in[0];
    const float* w[4] = {(const float*)d_in[1], (const float*)d_in[3],
                         (const float*)d_in[5], (const float*)d_in[7]};
    const float* bi[4] = {(const float*)d_in[2], (const float*)d_in[4],
                          (const float*)d_in[6], (const float*)d_in[8]};
    float* out = (float*)d_out;

    float* vb;
    cudaGetSymbolAddress((void**)&vb, g_V);
    __half *x16, *w16, *wo16, *q16, *k16, *vt16, *a16;
    cudaGetSymbolAddress((void**)&x16, g_x16);
    cudaGetSymbolAddress((void**)&w16, g_w16);
    cudaGetSymbolAddress((void**)&wo16, g_wo16);
    cudaGetSymbolAddress((void**)&q16, g_q16);
    cudaGetSymbolAddress((void**)&k16, g_k16);
    cudaGetSymbolAddress((void**)&vt16, g_vt16);
    cudaGetSymbolAddress((void**)&a16, g_a16);

    convert_x<<<ROWS * DMODEL / 1024, 256>>>(x, x16);
    convert_w<<<dim3(WN / 1024, 4), 256>>>(w[0], w[1], w[2], w[3], w16, wo16);

    size_t g16smem = 2 * STGE16 * sizeof(__half);
    cudaFuncSetAttribute(gemm_proj, cudaFuncAttributeMaxDynamicSharedMemorySize,
                         (int)g16smem);
    cudaFuncSetAttribute(gemm_f16, cudaFuncAttributeMaxDynamicSharedMemorySize,
                         (int)g16smem);
    gemm_proj<<<dim3(DMODEL / 128, ROWS / 128, 3), 256, g16smem>>>(
        x16, w16, bi[0], bi[1], bi[2], q16, k16, vb);

    convert_vt<<<dim3(SEQ / 32, DK / 32, BATCH * NHEADS), 256>>>(vb, vt16);

    size_t fsmem = FTOT * sizeof(__half);
    cudaFuncSetAttribute(flash_mma, cudaFuncAttributeMaxDynamicSharedMemorySize,
                         (int)fsmem);
    flash_mma<<<dim3(SEQ / 64, BATCH * NHEADS), 128, fsmem>>>(q16, k16, vt16, a16);

    gemm_f16<<<dim3(DMODEL / 128, ROWS / 128), 256, g16smem>>>(a16, wo16, bi[3], out);
}